// round 7
// baseline (speedup 1.0000x reference)
#include <cuda_runtime.h>
#include <math.h>
#include <stdint.h>
#include <mma.h>

using namespace nvcuda;

// ---------------- problem constants ----------------
#define DIMC   384
#define HEADS  6
#define HD     64
#define HIDDEN 1536
#define BATCH  4
#define NX     2048
#define NY     256
#define MTOK   2304
#define TTOK   (BATCH*MTOK)          // 9216
#define QKVN   (3*DIMC)              // 1152
#define ATT_SCALE 0.125f
#define LN_EPS 1e-5f

#define ATS 68                       // attention smem row stride
#define SMEM_ATTN (4*64*ATS*4)       // Ks, Vs, Ss, Os = 69,632 B

#define GAS (128*36)                 // one GEMM stage buffer (floats)
#define SMEM_GEMM ((4*GAS + 8*320)*4)   // 2 dbl-buffered tiles + epilogue = 83,968 B

#define NSPLIT 4                     // cross-attn K splits
#define KSPLIT (MTOK/NSPLIT)         // 576

// weight scratch offsets (tf32-rounded weights)
#define OFF_QKVW 0
#define OFF_PROJW (QKVN*DIMC)                      // 442368
#define OFF_FC1W  (OFF_PROJW + DIMC*DIMC)          // 589824
#define OFF_FC2W  (OFF_FC1W + HIDDEN*DIMC)         // 1179648
#define W_TOTAL   (OFF_FC2W + DIMC*HIDDEN)         // 1769472

// ---------------- scratch ----------------
__device__ float g_catln[TTOK*DIMC];
__device__ float g_qkv  [TTOK*QKVN];
__device__ float g_attno[TTOK*DIMC];
__device__ float g_ln2  [TTOK*DIMC];
__device__ float g_fc1  [TTOK*HIDDEN];
__device__ float g_wrnd [W_TOTAL];
__device__ float g_pO   [BATCH*HEADS*4*NSPLIT*64*64];   // cross partial O
__device__ float g_pML  [BATCH*HEADS*4*NSPLIT*128];     // cross partial m,l

// ---------------- helpers ----------------
__device__ __forceinline__ float f2tf32f(float f) {
    uint32_t u; asm("cvt.rna.tf32.f32 %0, %1;" : "=r"(u) : "f"(f));
    return __uint_as_float(u);
}
__device__ __forceinline__ void cp16(float* smem, const float* gmem) {
    uint32_t s = (uint32_t)__cvta_generic_to_shared(smem);
    asm volatile("cp.async.cg.shared.global [%0], [%1], 16;" :: "r"(s), "l"(gmem));
}
#define CP_COMMIT() asm volatile("cp.async.commit_group;")
#define CP_WAIT0()  asm volatile("cp.async.wait_group 0;")

// ---------------- weight pre-rounding ----------------
__global__ void round_weights(const float* __restrict__ qkvw, const float* __restrict__ projw,
                              const float* __restrict__ fc1w, const float* __restrict__ fc2w,
                              float* __restrict__ dst)
{
    int stride = gridDim.x * blockDim.x;
    int i0 = blockIdx.x * blockDim.x + threadIdx.x;
    for (int i = i0; i < QKVN*DIMC;  i += stride) dst[OFF_QKVW + i] = f2tf32f(qkvw[i]);
    for (int i = i0; i < DIMC*DIMC;  i += stride) dst[OFF_PROJW + i] = f2tf32f(projw[i]);
    for (int i = i0; i < HIDDEN*DIMC; i += stride) dst[OFF_FC1W + i] = f2tf32f(fc1w[i]);
    for (int i = i0; i < DIMC*HIDDEN; i += stride) dst[OFF_FC2W + i] = f2tf32f(fc2w[i]);
}

// ---------------- LayerNorm (stores tf32-rounded) ----------------
__global__ void __launch_bounds__(128) ln_kernel(
    const float* __restrict__ px, const float* __restrict__ py,
    const float* __restrict__ w,  const float* __restrict__ bsh,
    float* __restrict__ out)
{
    int t   = blockIdx.x;
    int bb  = t / MTOK;
    int pos = t - bb * MTOK;
    const float* src = (pos < NX)
        ? px + ((size_t)(bb*NX + pos)) * DIMC
        : py + ((size_t)(bb*NY + pos - NX)) * DIMC;

    int tid = threadIdx.x;
    float v0 = src[tid], v1 = src[tid+128], v2 = src[tid+256];
    float s  = v0 + v1 + v2;
    float sq = v0*v0 + v1*v1 + v2*v2;
    #pragma unroll
    for (int o = 16; o; o >>= 1) {
        s  += __shfl_xor_sync(0xffffffffu, s,  o);
        sq += __shfl_xor_sync(0xffffffffu, sq, o);
    }
    __shared__ float sm[4], sm2[4], stat[2];
    int wi = tid >> 5;
    if ((tid & 31) == 0) { sm[wi] = s; sm2[wi] = sq; }
    __syncthreads();
    if (tid == 0) {
        float S = sm[0]+sm[1]+sm[2]+sm[3];
        float Q = sm2[0]+sm2[1]+sm2[2]+sm2[3];
        float mean = S * (1.0f/DIMC);
        float var  = Q * (1.0f/DIMC) - mean*mean;
        stat[0] = mean;
        stat[1] = rsqrtf(var + LN_EPS);
    }
    __syncthreads();
    float mean = stat[0], inv = stat[1];
    float* op = out + (size_t)t * DIMC;
    op[tid]     = f2tf32f((v0-mean)*inv*w[tid]     + bsh[tid]);
    op[tid+128] = f2tf32f((v1-mean)*inv*w[tid+128] + bsh[tid+128]);
    op[tid+256] = f2tf32f((v2-mean)*inv*w[tid+256] + bsh[tid+256]);
}

// ---------------- per-element epilogue ----------------
// EPI 0: tf32-rounded store (qkv) | 1: +bias+input residual (proj, final)
// EPI 2: +bias+erf GELU, tf32-rounded (fc1) | 3: +bias+out residual (fc2, final)
template<int EPI>
__device__ __forceinline__ void epi_elem(int m, int n, float v, int N,
    const float* __restrict__ bias, float* __restrict__ C,
    const float* __restrict__ resx, const float* __restrict__ resy,
    float* __restrict__ outx, float* __restrict__ outy)
{
    if (EPI == 0) { C[(size_t)m*N + n] = f2tf32f(v); return; }
    float bv = bias[n];
    if (EPI == 2) {
        float x = v + bv;
        C[(size_t)m*N + n] = f2tf32f(0.5f * x * (1.0f + erff(x * 0.70710678118654752f)));
        return;
    }
    int bb  = m / MTOK;
    int pos = m - bb * MTOK;
    if (pos < NX) {
        size_t idx = ((size_t)(bb*NX + pos))*DIMC + n;
        float r = (EPI == 1) ? resx[idx] : outx[idx];
        outx[idx] = v + bv + r;
    } else {
        size_t idx = ((size_t)(bb*NY + pos - NX))*DIMC + n;
        float r = (EPI == 1) ? resy[idx] : outy[idx];
        outy[idx] = v + bv + r;
    }
}

// ---------------- double-buffered wmma tf32 GEMM ----------------
// C[M,N] = A[M,K] * W[N,K]^T. Block 128x128, 8 warps (4x2), warp tile 32x64.
// Inputs are pre-rounded tf32; staging is pure cp.async copies.
__device__ __forceinline__ void stage_tiles(
    const float* __restrict__ A, const float* __restrict__ W,
    float* Ab, float* Wb, int m0, int n0, int k0, int K, int tid)
{
    #pragma unroll
    for (int i = 0; i < 4; i++) {
        int idx = tid + i*256;
        int row = idx >> 3, c4 = (idx & 7) << 2;
        cp16(Ab + row*36 + c4, A + (size_t)(m0+row)*K + k0 + c4);
    }
    #pragma unroll
    for (int i = 0; i < 4; i++) {
        int idx = tid + i*256;
        int row = idx >> 3, c4 = (idx & 7) << 2;
        cp16(Wb + row*36 + c4, W + (size_t)(n0+row)*K + k0 + c4);
    }
    CP_COMMIT();
}

template<int EPI>
__global__ void __launch_bounds__(256) gemm_db(
    const float* __restrict__ A, const float* __restrict__ W,
    const float* __restrict__ bias, float* __restrict__ C,
    int M, int N, int K,
    const float* __restrict__ resx, const float* __restrict__ resy,
    float* __restrict__ outx, float* __restrict__ outy)
{
    extern __shared__ __align__(16) float sgm[];
    float* Ab[2] = { sgm,          sgm + 2*GAS };
    float* Wb[2] = { sgm + GAS,    sgm + 3*GAS };
    float* Ct    = sgm + 4*GAS;     // 8 warps * 320

    int tid = threadIdx.x, w = tid >> 5, lane = tid & 31;
    int wm = w >> 1, wn = w & 1;
    int m0 = blockIdx.y << 7, n0 = blockIdx.x << 7;

    wmma::fragment<wmma::accumulator, 16, 16, 8, float> acc[2][4];
    #pragma unroll
    for (int i = 0; i < 2; i++)
        #pragma unroll
        for (int j = 0; j < 4; j++) wmma::fill_fragment(acc[i][j], 0.0f);

    int T = K >> 5;
    stage_tiles(A, W, Ab[0], Wb[0], m0, n0, 0, K, tid);

    for (int t = 0; t < T; t++) {
        CP_WAIT0();
        __syncthreads();
        if (t + 1 < T)
            stage_tiles(A, W, Ab[(t+1)&1], Wb[(t+1)&1], m0, n0, (t+1)<<5, K, tid);
        float* Ac = Ab[t&1];
        float* Wc = Wb[t&1];
        #pragma unroll
        for (int ks = 0; ks < 4; ks++) {
            int kb = ks << 3;
            wmma::fragment<wmma::matrix_a, 16, 16, 8, wmma::precision::tf32, wmma::row_major> af[2];
            wmma::fragment<wmma::matrix_b, 16, 16, 8, wmma::precision::tf32, wmma::col_major> bf[4];
            wmma::load_matrix_sync(af[0], Ac + (wm*32     )*36 + kb, 36);
            wmma::load_matrix_sync(af[1], Ac + (wm*32 + 16)*36 + kb, 36);
            #pragma unroll
            for (int j = 0; j < 4; j++)
                wmma::load_matrix_sync(bf[j], Wc + (wn*64 + j*16)*36 + kb, 36);
            #pragma unroll
            for (int i = 0; i < 2; i++)
                #pragma unroll
                for (int j = 0; j < 4; j++)
                    wmma::mma_sync(acc[i][j], af[i], bf[j], acc[i][j]);
        }
        __syncthreads();
    }

    float* myCt = Ct + w*320;
    #pragma unroll
    for (int i = 0; i < 2; i++) {
        #pragma unroll
        for (int j = 0; j < 4; j++) {
            wmma::store_matrix_sync(myCt, acc[i][j], 20, wmma::mem_row_major);
            __syncwarp();
            int r  = lane >> 1;
            int cb = (lane & 1) << 3;
            int mg = m0 + wm*32 + i*16 + r;
            int ng = n0 + wn*64 + j*16 + cb;
            #pragma unroll
            for (int q = 0; q < 8; q++)
                epi_elem<EPI>(mg, ng + q, myCt[r*20 + cb + q], N, bias, C, resx, resy, outx, outy);
            __syncwarp();
        }
    }
}

// ---------------- wmma tf32 flash attention (optionally split-K) ----------------
// 64 q/block, 4 warps x 16 rows. qkv pre-rounded tf32 -> staging is pure copies.
template<bool SPLIT>
__global__ void __launch_bounds__(128) attn_wmma(
    const float* __restrict__ qkv, float* __restrict__ attno,
    float* __restrict__ pO, float* __restrict__ pML,
    int q_base, int klen_arg)
{
    extern __shared__ __align__(16) float dyn[];
    float* Ks = dyn;
    float* Vs = Ks + 64*ATS;
    float* Ss = Vs + 64*ATS;
    float* Os = Ss + 64*ATS;
    __shared__ float sm_m[64], sm_l[64];

    int tid = threadIdx.x, w = tid >> 5, lane = tid & 31;
    int h = blockIdx.y, b = blockIdx.z;
    int qb, sp, q0, k_off, k_len;
    if (SPLIT) {
        qb = blockIdx.x >> 2; sp = blockIdx.x & 3;
        q0 = q_base + (qb << 6);
        k_off = sp * klen_arg; k_len = klen_arg;
    } else {
        qb = blockIdx.x; sp = 0;
        q0 = q_base + (qb << 6);
        k_off = 0; k_len = klen_arg;
    }

    // stage Q (x ATT_SCALE, exact in tf32)
    #pragma unroll
    for (int i = 0; i < 8; i++) {
        int idx = tid + i*128;
        int row = idx >> 4, c4 = (idx & 15) << 2;
        float4 v = *(const float4*)(qkv + ((size_t)(b*MTOK + q0 + row))*QKVN + h*HD + c4);
        float* d = Ss + row*ATS + c4;
        d[0]=v.x*ATT_SCALE; d[1]=v.y*ATT_SCALE; d[2]=v.z*ATT_SCALE; d[3]=v.w*ATT_SCALE;
    }
    __syncthreads();

    wmma::fragment<wmma::matrix_a, 16, 16, 8, wmma::precision::tf32, wmma::row_major> qa[8];
    #pragma unroll
    for (int kk = 0; kk < 8; kk++)
        wmma::load_matrix_sync(qa[kk], Ss + (w*16)*ATS + kk*8, ATS);

    for (int i = tid; i < 64*ATS; i += 128) Os[i] = 0.f;
    if (tid < 64) { sm_m[tid] = -INFINITY; sm_l[tid] = 0.f; }
    __syncthreads();

    const float* kbase = qkv + ((size_t)b*MTOK)*QKVN + DIMC   + h*HD;
    const float* vbase = qkv + ((size_t)b*MTOK)*QKVN + 2*DIMC + h*HD;

    for (int kt = k_off; kt < k_off + k_len; kt += 64) {
        #pragma unroll
        for (int i = 0; i < 8; i++) {
            int idx = tid + i*128;
            int row = idx >> 4, c4 = (idx & 15) << 2;
            *(float4*)(Ks + row*ATS + c4) = *(const float4*)(kbase + (size_t)(kt+row)*QKVN + c4);
            *(float4*)(Vs + row*ATS + c4) = *(const float4*)(vbase + (size_t)(kt+row)*QKVN + c4);
        }
        __syncthreads();

        // S = Q @ K^T
        #pragma unroll
        for (int j = 0; j < 4; j++) {
            wmma::fragment<wmma::accumulator, 16, 16, 8, float> sacc;
            wmma::fill_fragment(sacc, 0.0f);
            #pragma unroll
            for (int kk = 0; kk < 8; kk++) {
                wmma::fragment<wmma::matrix_b, 16, 16, 8, wmma::precision::tf32, wmma::col_major> kf;
                wmma::load_matrix_sync(kf, Ks + (j*16)*ATS + kk*8, ATS);
                wmma::mma_sync(sacc, qa[kk], kf, sacc);
            }
            wmma::store_matrix_sync(Ss + (w*16)*ATS + j*16, sacc, ATS, wmma::mem_row_major);
        }
        __syncwarp();

        // online softmax on this warp's 16 rows
        {
            int r  = lane >> 1;
            int hf = lane & 1;
            int row = w*16 + r;
            float* srow = Ss + row*ATS + hf*32;
            float mold = sm_m[row];
            float tmax = mold;
            #pragma unroll
            for (int c = 0; c < 32; c++) tmax = fmaxf(tmax, srow[c]);
            tmax = fmaxf(tmax, __shfl_xor_sync(0xffffffffu, tmax, 1));
            float corr = __expf(mold - tmax);
            float psum = 0.f;
            #pragma unroll
            for (int c = 0; c < 32; c++) {
                float p = __expf(srow[c] - tmax);
                psum += p;
                srow[c] = f2tf32f(p);
            }
            psum += __shfl_xor_sync(0xffffffffu, psum, 1);
            if (hf == 0) {
                sm_m[row] = tmax;
                sm_l[row] = sm_l[row]*corr + psum;
            }
            float* orow = Os + row*ATS + hf*32;
            #pragma unroll
            for (int c = 0; c < 32; c++) orow[c] *= corr;
        }
        __syncwarp();

        // O += P @ V
        wmma::fragment<wmma::matrix_a, 16, 16, 8, wmma::precision::tf32, wmma::row_major> pa[8];
        #pragma unroll
        for (int kk = 0; kk < 8; kk++)
            wmma::load_matrix_sync(pa[kk], Ss + (w*16)*ATS + kk*8, ATS);
        #pragma unroll
        for (int j = 0; j < 4; j++) {
            wmma::fragment<wmma::accumulator, 16, 16, 8, float> oacc;
            wmma::load_matrix_sync(oacc, Os + (w*16)*ATS + j*16, ATS, wmma::mem_row_major);
            #pragma unroll
            for (int kk = 0; kk < 8; kk++) {
                wmma::fragment<wmma::matrix_b, 16, 16, 8, wmma::precision::tf32, wmma::row_major> vf;
                wmma::load_matrix_sync(vf, Vs + (kk*8)*ATS + j*16, ATS);
                wmma::mma_sync(oacc, pa[kk], vf, oacc);
            }
            wmma::store_matrix_sync(Os + (w*16)*ATS + j*16, oacc, ATS, wmma::mem_row_major);
        }
        __syncthreads();
    }

    if (SPLIT) {
        int pidx = ((b*HEADS + h)*4 + qb)*NSPLIT + sp;
        // unnormalized O + (m, l)
        int r  = tid >> 1;
        int hf = tid & 1;
        float* dst = pO + (size_t)pidx*4096 + r*64 + hf*32;
        const float* orow = Os + r*ATS + hf*32;
        #pragma unroll
        for (int c4 = 0; c4 < 8; c4++)
            *(float4*)(dst + c4*4) = *(const float4*)(orow + c4*4);
        if (tid < 64) {
            pML[pidx*128 + tid]      = sm_m[tid];
            pML[pidx*128 + 64 + tid] = sm_l[tid];
        }
    } else {
        int r  = tid >> 1;
        int hf = tid & 1;
        float inv = 1.f / sm_l[r];
        const float* orow = Os + r*ATS + hf*32;
        float* op = attno + ((size_t)(b*MTOK + q0 + r))*DIMC + h*HD + hf*32;
        #pragma unroll
        for (int c4 = 0; c4 < 8; c4++) {
            float4 o = *(const float4*)(orow + c4*4);
            op[c4*4+0]=f2tf32f(o.x*inv); op[c4*4+1]=f2tf32f(o.y*inv);
            op[c4*4+2]=f2tf32f(o.z*inv); op[c4*4+3]=f2tf32f(o.w*inv);
        }
    }
}

// ---------------- merge split-K partials (cross attention) ----------------
__global__ void __launch_bounds__(64) merge_attn(
    const float* __restrict__ pO, const float* __restrict__ pML,
    float* __restrict__ attno)
{
    int qb = blockIdx.x, h = blockIdx.y, b = blockIdx.z;
    int r = threadIdx.x;
    int base = ((b*HEADS + h)*4 + qb)*NSPLIT;

    float mx = -INFINITY;
    #pragma unroll
    for (int s = 0; s < NSPLIT; s++)
        mx = fmaxf(mx, pML[(base+s)*128 + r]);
    float wgt[NSPLIT];
    float L = 0.f;
    #pragma unroll
    for (int s = 0; s < NSPLIT; s++) {
        wgt[s] = __expf(pML[(base+s)*128 + r] - mx);
        L += wgt[s] * pML[(base+s)*128 + 64 + r];
    }
    float inv = 1.f / L;
    int qi = NX + (qb << 6) + r;
    float* op = attno + ((size_t)(b*MTOK + qi))*DIMC + h*HD;
    #pragma unroll 4
    for (int c = 0; c < 64; c++) {
        float o = 0.f;
        #pragma unroll
        for (int s = 0; s < NSPLIT; s++)
            o += wgt[s] * pO[(size_t)(base+s)*4096 + r*64 + c];
        op[c] = f2tf32f(o * inv);
    }
}

// ---------------- launch ----------------
extern "C" void kernel_launch(void* const* d_in, const int* in_sizes, int n_in,
                              void* d_out, int out_size)
{
    const float* x     = (const float*)d_in[0];
    const float* y     = (const float*)d_in[1];
    const float* n1w   = (const float*)d_in[2];
    const float* n1b   = (const float*)d_in[3];
    const float* n2w   = (const float*)d_in[4];
    const float* n2b   = (const float*)d_in[5];
    const float* qkvw  = (const float*)d_in[6];
    const float* projw = (const float*)d_in[7];
    const float* projb = (const float*)d_in[8];
    const float* fc1w  = (const float*)d_in[9];
    const float* fc1bb = (const float*)d_in[10];
    const float* fc2w  = (const float*)d_in[11];
    const float* fc2b  = (const float*)d_in[12];
    (void)in_sizes; (void)n_in; (void)out_size;

    float* outx = (float*)d_out;
    float* outy = outx + (size_t)BATCH*NX*DIMC;

    float *catln, *qkvb, *attno, *ln2o, *fc1o, *wrnd, *pO, *pML;
    cudaGetSymbolAddress((void**)&catln, g_catln);
    cudaGetSymbolAddress((void**)&qkvb,  g_qkv);
    cudaGetSymbolAddress((void**)&attno, g_attno);
    cudaGetSymbolAddress((void**)&ln2o,  g_ln2);
    cudaGetSymbolAddress((void**)&fc1o,  g_fc1);
    cudaGetSymbolAddress((void**)&wrnd,  g_wrnd);
    cudaGetSymbolAddress((void**)&pO,    g_pO);
    cudaGetSymbolAddress((void**)&pML,   g_pML);

    cudaFuncSetAttribute(gemm_db<0>, cudaFuncAttributeMaxDynamicSharedMemorySize, SMEM_GEMM);
    cudaFuncSetAttribute(gemm_db<1>, cudaFuncAttributeMaxDynamicSharedMemorySize, SMEM_GEMM);
    cudaFuncSetAttribute(gemm_db<2>, cudaFuncAttributeMaxDynamicSharedMemorySize, SMEM_GEMM);
    cudaFuncSetAttribute(gemm_db<3>, cudaFuncAttributeMaxDynamicSharedMemorySize, SMEM_GEMM);
    cudaFuncSetAttribute(attn_wmma<false>, cudaFuncAttributeMaxDynamicSharedMemorySize, SMEM_ATTN);
    cudaFuncSetAttribute(attn_wmma<true>,  cudaFuncAttributeMaxDynamicSharedMemorySize, SMEM_ATTN);

    // 0) pre-round weights to tf32
    round_weights<<<256, 256>>>(qkvw, projw, fc1w, fc2w, wrnd);
    // 1) LN1 over concat(x, y)
    ln_kernel<<<TTOK, 128>>>(x, y, n1w, n1b, catln);
    // 2) fused QKV GEMM
    gemm_db<0><<<dim3(QKVN/128, TTOK/128), 256, SMEM_GEMM>>>(catln, wrnd + OFF_QKVW, nullptr, qkvb,
        TTOK, QKVN, DIMC, nullptr, nullptr, nullptr, nullptr);
    // 3) x self-attention
    attn_wmma<false><<<dim3(NX/64, HEADS, BATCH), 128, SMEM_ATTN>>>(qkvb, attno, nullptr, nullptr, 0, NX);
    // 4) y cross-attention, split-K x4 + merge
    attn_wmma<true><<<dim3((NY/64)*NSPLIT, HEADS, BATCH), 128, SMEM_ATTN>>>(qkvb, nullptr, pO, pML, NX, KSPLIT);
    merge_attn<<<dim3(NY/64, HEADS, BATCH), 64>>>(pO, pML, attno);
    // 5) output projection + bias + input residual -> d_out
    gemm_db<1><<<dim3(DIMC/128, TTOK/128), 256, SMEM_GEMM>>>(attno, wrnd + OFF_PROJW, projb, nullptr,
        TTOK, DIMC, DIMC, x, y, outx, outy);
    // 6) LN2 over d_out
    ln_kernel<<<TTOK, 128>>>(outx, outy, n2w, n2b, ln2o);
    // 7) fc1 + bias + exact GELU
    gemm_db<2><<<dim3(HIDDEN/128, TTOK/128), 256, SMEM_GEMM>>>(ln2o, wrnd + OFF_FC1W, fc1bb, fc1o,
        TTOK, HIDDEN, DIMC, nullptr, nullptr, nullptr, nullptr);
    // 8) fc2 + bias + residual (in place on d_out)
    gemm_db<3><<<dim3(DIMC/128, TTOK/128), 256, SMEM_GEMM>>>(fc1o, wrnd + OFF_FC2W, fc2b, nullptr,
        TTOK, DIMC, HIDDEN, nullptr, nullptr, outx, outy);
}

// round 8
// speedup vs baseline: 1.0995x; 1.0995x over previous
#include <cuda_runtime.h>
#include <math.h>
#include <stdint.h>
#include <mma.h>

using namespace nvcuda;

// ---------------- problem constants ----------------
#define DIMC   384
#define HEADS  6
#define HD     64
#define HIDDEN 1536
#define BATCH  4
#define NX     2048
#define NY     256
#define MTOK   2304
#define TTOK   (BATCH*MTOK)          // 9216
#define QKVN   (3*DIMC)              // 1152
#define ATT_SCALE 0.125f
#define LN_EPS 1e-5f

#define ATS 68                       // attention smem row stride
// dyn smem: Kb[2] + Vb[2] (64 rows each) + Ss (128 rows)
#define SMEM_ATTN ((4*64*ATS + 128*ATS)*4)

#define NSPLIT 4
#define KSPLIT (MTOK/NSPLIT)         // 576
#define QBY    (NY/128)              // 2 cross q-blocks

// weight scratch offsets (tf32-rounded weights)
#define OFF_QKVW 0
#define OFF_PROJW (QKVN*DIMC)
#define OFF_FC1W  (OFF_PROJW + DIMC*DIMC)
#define OFF_FC2W  (OFF_FC1W + HIDDEN*DIMC)
#define W_TOTAL   (OFF_FC2W + DIMC*HIDDEN)

// ---------------- scratch ----------------
__device__ float g_catln[TTOK*DIMC];
__device__ float g_qkv  [TTOK*QKVN];
__device__ float g_attno[TTOK*DIMC];
__device__ float g_ln2  [TTOK*DIMC];
__device__ float g_fc1  [TTOK*HIDDEN];
__device__ float g_wrnd [W_TOTAL];
__device__ float g_pO   [BATCH*HEADS*QBY*NSPLIT*128*64];
__device__ float g_pL   [BATCH*HEADS*QBY*NSPLIT*128];

// ---------------- helpers ----------------
__device__ __forceinline__ float f2tf32f(float f) {
    uint32_t u; asm("cvt.rna.tf32.f32 %0, %1;" : "=r"(u) : "f"(f));
    return __uint_as_float(u);
}
__device__ __forceinline__ void cp16(float* smem, const float* gmem) {
    uint32_t s = (uint32_t)__cvta_generic_to_shared(smem);
    asm volatile("cp.async.cg.shared.global [%0], [%1], 16;" :: "r"(s), "l"(gmem));
}
#define CP_COMMIT() asm volatile("cp.async.commit_group;")
#define CP_WAIT0()  asm volatile("cp.async.wait_group 0;")

// ---------------- weight pre-rounding ----------------
__global__ void round_weights(const float* __restrict__ qkvw, const float* __restrict__ projw,
                              const float* __restrict__ fc1w, const float* __restrict__ fc2w,
                              float* __restrict__ dst)
{
    int stride = gridDim.x * blockDim.x;
    int i0 = blockIdx.x * blockDim.x + threadIdx.x;
    for (int i = i0; i < QKVN*DIMC;  i += stride) dst[OFF_QKVW + i]  = f2tf32f(qkvw[i]);
    for (int i = i0; i < DIMC*DIMC;  i += stride) dst[OFF_PROJW + i] = f2tf32f(projw[i]);
    for (int i = i0; i < HIDDEN*DIMC; i += stride) dst[OFF_FC1W + i] = f2tf32f(fc1w[i]);
    for (int i = i0; i < DIMC*HIDDEN; i += stride) dst[OFF_FC2W + i] = f2tf32f(fc2w[i]);
}

// ---------------- LayerNorm (stores tf32-rounded) ----------------
__global__ void __launch_bounds__(128) ln_kernel(
    const float* __restrict__ px, const float* __restrict__ py,
    const float* __restrict__ w,  const float* __restrict__ bsh,
    float* __restrict__ out)
{
    int t   = blockIdx.x;
    int bb  = t / MTOK;
    int pos = t - bb * MTOK;
    const float* src = (pos < NX)
        ? px + ((size_t)(bb*NX + pos)) * DIMC
        : py + ((size_t)(bb*NY + pos - NX)) * DIMC;

    int tid = threadIdx.x;
    float v0 = src[tid], v1 = src[tid+128], v2 = src[tid+256];
    float s  = v0 + v1 + v2;
    float sq = v0*v0 + v1*v1 + v2*v2;
    #pragma unroll
    for (int o = 16; o; o >>= 1) {
        s  += __shfl_xor_sync(0xffffffffu, s,  o);
        sq += __shfl_xor_sync(0xffffffffu, sq, o);
    }
    __shared__ float sm[4], sm2[4], stat[2];
    int wi = tid >> 5;
    if ((tid & 31) == 0) { sm[wi] = s; sm2[wi] = sq; }
    __syncthreads();
    if (tid == 0) {
        float S = sm[0]+sm[1]+sm[2]+sm[3];
        float Q = sm2[0]+sm2[1]+sm2[2]+sm2[3];
        float mean = S * (1.0f/DIMC);
        float var  = Q * (1.0f/DIMC) - mean*mean;
        stat[0] = mean;
        stat[1] = rsqrtf(var + LN_EPS);
    }
    __syncthreads();
    float mean = stat[0], inv = stat[1];
    float* op = out + (size_t)t * DIMC;
    op[tid]     = f2tf32f((v0-mean)*inv*w[tid]     + bsh[tid]);
    op[tid+128] = f2tf32f((v1-mean)*inv*w[tid+128] + bsh[tid+128]);
    op[tid+256] = f2tf32f((v2-mean)*inv*w[tid+256] + bsh[tid+256]);
}

// ---------------- per-element epilogue ----------------
template<int EPI>
__device__ __forceinline__ void epi_elem(int m, int n, float v, int N,
    const float* __restrict__ bias, float* __restrict__ C,
    const float* __restrict__ resx, const float* __restrict__ resy,
    float* __restrict__ outx, float* __restrict__ outy)
{
    if (EPI == 0) { C[(size_t)m*N + n] = f2tf32f(v); return; }
    float bv = bias[n];
    if (EPI == 2) {
        float x = v + bv;
        C[(size_t)m*N + n] = f2tf32f(0.5f * x * (1.0f + erff(x * 0.70710678118654752f)));
        return;
    }
    int bb  = m / MTOK;
    int pos = m - bb * MTOK;
    if (pos < NX) {
        size_t idx = ((size_t)(bb*NX + pos))*DIMC + n;
        float r = (EPI == 1) ? resx[idx] : outx[idx];
        outx[idx] = v + bv + r;
    } else {
        size_t idx = ((size_t)(bb*NY + pos - NX))*DIMC + n;
        float r = (EPI == 1) ? resy[idx] : outy[idx];
        outy[idx] = v + bv + r;
    }
}

// ---------------- staged wmma tf32 GEMM (R6-proven): C = A * W^T ----------------
// block tile 128x64, 8 warps (4x2), warp tile 32x32, k-tile 32. Inputs pre-rounded.
template<int EPI>
__global__ void __launch_bounds__(256) gemm_wmma(
    const float* __restrict__ A, const float* __restrict__ W,
    const float* __restrict__ bias, float* __restrict__ C,
    int M, int N, int K,
    const float* __restrict__ resx, const float* __restrict__ resy,
    float* __restrict__ outx, float* __restrict__ outy)
{
    __shared__ __align__(16) float As[128*36];
    __shared__ __align__(16) float Ws[64*36];
    __shared__ __align__(16) float Ct[8][16*20];

    int tid = threadIdx.x;
    int w = tid >> 5, lane = tid & 31;
    int wm = w >> 1, wn = w & 1;
    int m0 = blockIdx.y << 7;
    int n0 = blockIdx.x << 6;

    wmma::fragment<wmma::accumulator, 16, 16, 8, float> acc[2][2];
    #pragma unroll
    for (int i = 0; i < 2; i++)
        #pragma unroll
        for (int j = 0; j < 2; j++) wmma::fill_fragment(acc[i][j], 0.0f);

    for (int k0 = 0; k0 < K; k0 += 32) {
        #pragma unroll
        for (int i = 0; i < 4; i++) {
            int idx = tid + i*256;
            int row = idx >> 3, c4 = (idx & 7) << 2;
            *(float4*)(As + row*36 + c4) = *(const float4*)(A + (size_t)(m0+row)*K + k0 + c4);
        }
        #pragma unroll
        for (int i = 0; i < 2; i++) {
            int idx = tid + i*256;
            int row = idx >> 3, c4 = (idx & 7) << 2;
            *(float4*)(Ws + row*36 + c4) = *(const float4*)(W + (size_t)(n0+row)*K + k0 + c4);
        }
        __syncthreads();

        #pragma unroll
        for (int ks = 0; ks < 4; ks++) {
            int kb = ks << 3;
            wmma::fragment<wmma::matrix_a, 16, 16, 8, wmma::precision::tf32, wmma::row_major> af[2];
            wmma::fragment<wmma::matrix_b, 16, 16, 8, wmma::precision::tf32, wmma::col_major> bf[2];
            wmma::load_matrix_sync(af[0], As + (wm*32     )*36 + kb, 36);
            wmma::load_matrix_sync(af[1], As + (wm*32 + 16)*36 + kb, 36);
            wmma::load_matrix_sync(bf[0], Ws + (wn*32     )*36 + kb, 36);
            wmma::load_matrix_sync(bf[1], Ws + (wn*32 + 16)*36 + kb, 36);
            #pragma unroll
            for (int i = 0; i < 2; i++)
                #pragma unroll
                for (int j = 0; j < 2; j++)
                    wmma::mma_sync(acc[i][j], af[i], bf[j], acc[i][j]);
        }
        __syncthreads();
    }

    #pragma unroll
    for (int i = 0; i < 2; i++) {
        #pragma unroll
        for (int j = 0; j < 2; j++) {
            wmma::store_matrix_sync(&Ct[w][0], acc[i][j], 20, wmma::mem_row_major);
            __syncwarp();
            int r  = lane >> 1;
            int cb = (lane & 1) << 3;
            int mg = m0 + wm*32 + i*16 + r;
            int ng = n0 + wn*32 + j*16 + cb;
            #pragma unroll
            for (int q = 0; q < 8; q++)
                epi_elem<EPI>(mg, ng + q, Ct[w][r*20 + cb + q], N, bias, C, resx, resy, outx, outy);
            __syncwarp();
        }
    }
}

// ---------------- attention v2: no-max softmax, register-resident O ----------------
// 128 q/block, 8 warps x 16 rows; cp.async double-buffered K/V tiles of 64 keys.
template<bool SPLIT>
__global__ void __launch_bounds__(256) attn_v2(
    const float* __restrict__ qkv, float* __restrict__ attno,
    float* __restrict__ pO, float* __restrict__ pL,
    int q_base, int klen)
{
    extern __shared__ __align__(16) float dyn[];
    float* Kb[2] = { dyn,            dyn + 64*ATS };
    float* Vb[2] = { dyn + 2*64*ATS, dyn + 3*64*ATS };
    float* Ss    = dyn + 4*64*ATS;           // [128][ATS]

    int tid = threadIdx.x, w = tid >> 5, lane = tid & 31;
    int h = blockIdx.y, b = blockIdx.z;
    int qb, sp;
    if (SPLIT) { qb = blockIdx.x >> 2; sp = blockIdx.x & 3; }
    else       { qb = blockIdx.x;      sp = 0; }
    int q0   = q_base + (qb << 7);
    int koff = SPLIT ? sp * klen : 0;

    // stage Q (x ATT_SCALE; qkv pre-rounded, 0.125 exact in tf32)
    #pragma unroll
    for (int i = 0; i < 8; i++) {
        int idx = tid + i*256;
        int row = idx >> 4, c4 = (idx & 15) << 2;
        float4 v = *(const float4*)(qkv + ((size_t)(b*MTOK + q0 + row))*QKVN + h*HD + c4);
        float* d = Ss + row*ATS + c4;
        d[0]=v.x*ATT_SCALE; d[1]=v.y*ATT_SCALE; d[2]=v.z*ATT_SCALE; d[3]=v.w*ATT_SCALE;
    }
    __syncthreads();

    wmma::fragment<wmma::matrix_a, 16, 16, 8, wmma::precision::tf32, wmma::row_major> qa[8];
    #pragma unroll
    for (int kk = 0; kk < 8; kk++)
        wmma::load_matrix_sync(qa[kk], Ss + (w*16)*ATS + kk*8, ATS);

    wmma::fragment<wmma::accumulator, 16, 16, 8, float> oacc[4];
    #pragma unroll
    for (int j = 0; j < 4; j++) wmma::fill_fragment(oacc[j], 0.0f);
    float lreg = 0.f;

    const float* kbase = qkv + ((size_t)b*MTOK)*QKVN + DIMC   + h*HD;
    const float* vbase = qkv + ((size_t)b*MTOK)*QKVN + 2*DIMC + h*HD;

    int T = klen >> 6;
    // stage tile 0
    {
        int kt = koff;
        #pragma unroll
        for (int i = 0; i < 4; i++) {
            int idx = tid + i*256;
            int row = idx >> 4, c4 = (idx & 15) << 2;
            cp16(Kb[0] + row*ATS + c4, kbase + (size_t)(kt+row)*QKVN + c4);
            cp16(Vb[0] + row*ATS + c4, vbase + (size_t)(kt+row)*QKVN + c4);
        }
        CP_COMMIT();
    }

    for (int t = 0; t < T; t++) {
        CP_WAIT0();
        __syncthreads();
        if (t + 1 < T) {
            int kt = koff + ((t+1) << 6);
            float* Kn = Kb[(t+1)&1];
            float* Vn = Vb[(t+1)&1];
            #pragma unroll
            for (int i = 0; i < 4; i++) {
                int idx = tid + i*256;
                int row = idx >> 4, c4 = (idx & 15) << 2;
                cp16(Kn + row*ATS + c4, kbase + (size_t)(kt+row)*QKVN + c4);
                cp16(Vn + row*ATS + c4, vbase + (size_t)(kt+row)*QKVN + c4);
            }
            CP_COMMIT();
        }
        float* Ks = Kb[t&1];
        float* Vs = Vb[t&1];

        // S = Q @ K^T -> Ss (own 16 rows)
        #pragma unroll
        for (int j = 0; j < 4; j++) {
            wmma::fragment<wmma::accumulator, 16, 16, 8, float> sacc;
            wmma::fill_fragment(sacc, 0.0f);
            #pragma unroll
            for (int kk = 0; kk < 8; kk++) {
                wmma::fragment<wmma::matrix_b, 16, 16, 8, wmma::precision::tf32, wmma::col_major> kf;
                wmma::load_matrix_sync(kf, Ks + (j*16)*ATS + kk*8, ATS);
                wmma::mma_sync(sacc, qa[kk], kf, sacc);
            }
            wmma::store_matrix_sync(Ss + (w*16)*ATS + j*16, sacc, ATS, wmma::mem_row_major);
        }
        __syncwarp();

        // no-max softmax: P = exp(S), accumulate row sum
        {
            int r  = lane >> 1;
            int hf = lane & 1;
            float* srow = Ss + (w*16 + r)*ATS + hf*32;
            float ps = 0.f;
            #pragma unroll
            for (int c = 0; c < 32; c++) {
                float p = __expf(srow[c]);
                ps += p;
                srow[c] = f2tf32f(p);
            }
            lreg += ps;
        }
        __syncwarp();

        // O += P @ V  (O stays in registers)
        wmma::fragment<wmma::matrix_a, 16, 16, 8, wmma::precision::tf32, wmma::row_major> pa[8];
        #pragma unroll
        for (int kk = 0; kk < 8; kk++)
            wmma::load_matrix_sync(pa[kk], Ss + (w*16)*ATS + kk*8, ATS);
        #pragma unroll
        for (int j = 0; j < 4; j++) {
            #pragma unroll
            for (int kk = 0; kk < 8; kk++) {
                wmma::fragment<wmma::matrix_b, 16, 16, 8, wmma::precision::tf32, wmma::row_major> vf;
                wmma::load_matrix_sync(vf, Vs + (kk*8)*ATS + j*16, ATS);
                wmma::mma_sync(oacc[j], pa[kk], vf, oacc[j]);
            }
        }
        // buffer-reuse safety provided by the syncthreads at top of next iter
    }

    // dump O to own Ss rows, then write out
    #pragma unroll
    for (int j = 0; j < 4; j++)
        wmma::store_matrix_sync(Ss + (w*16)*ATS + j*16, oacc[j], ATS, wmma::mem_row_major);
    __syncwarp();

    float ltot = lreg + __shfl_xor_sync(0xffffffffu, lreg, 1);
    int r  = lane >> 1;
    int hf = lane & 1;
    int row = w*16 + r;
    const float* orow = Ss + row*ATS + hf*32;

    if (SPLIT) {
        int pidx = ((b*HEADS + h)*QBY + qb)*NSPLIT + sp;
        float* dst = pO + (size_t)pidx*(128*64) + row*64 + hf*32;
        #pragma unroll
        for (int c4 = 0; c4 < 8; c4++)
            *(float4*)(dst + c4*4) = *(const float4*)(orow + c4*4);
        if (hf == 0) pL[pidx*128 + row] = ltot;
    } else {
        float inv = 1.f / ltot;
        float* op = attno + ((size_t)(b*MTOK + q0 + row))*DIMC + h*HD + hf*32;
        #pragma unroll
        for (int c = 0; c < 32; c++) op[c] = f2tf32f(orow[c]*inv);
    }
}

// ---------------- merge split-K partials (simple sums; no-max softmax) ----------------
__global__ void __launch_bounds__(128) merge_attn(
    const float* __restrict__ pO, const float* __restrict__ pL,
    float* __restrict__ attno)
{
    int qb = blockIdx.x, h = blockIdx.y, b = blockIdx.z;
    int r = threadIdx.x;            // 0..127
    int base = ((b*HEADS + h)*QBY + qb)*NSPLIT;

    float L = 0.f;
    #pragma unroll
    for (int s = 0; s < NSPLIT; s++) L += pL[(base+s)*128 + r];
    float inv = 1.f / L;

    int qi = NX + (qb << 7) + r;
    float* op = attno + ((size_t)(b*MTOK + qi))*DIMC + h*HD;
    #pragma unroll 4
    for (int c = 0; c < 64; c++) {
        float o = 0.f;
        #pragma unroll
        for (int s = 0; s < NSPLIT; s++)
            o += pO[(size_t)(base+s)*(128*64) + r*64 + c];
        op[c] = f2tf32f(o * inv);
    }
}

// ---------------- launch ----------------
extern "C" void kernel_launch(void* const* d_in, const int* in_sizes, int n_in,
                              void* d_out, int out_size)
{
    const float* x     = (const float*)d_in[0];
    const float* y     = (const float*)d_in[1];
    const float* n1w   = (const float*)d_in[2];
    const float* n1b   = (const float*)d_in[3];
    const float* n2w   = (const float*)d_in[4];
    const float* n2b   = (const float*)d_in[5];
    const float* qkvw  = (const float*)d_in[6];
    const float* projw = (const float*)d_in[7];
    const float* projb = (const float*)d_in[8];
    const float* fc1w  = (const float*)d_in[9];
    const float* fc1bb = (const float*)d_in[10];
    const float* fc2w  = (const float*)d_in[11];
    const float* fc2b  = (const float*)d_in[12];
    (void)in_sizes; (void)n_in; (void)out_size;

    float* outx = (float*)d_out;
    float* outy = outx + (size_t)BATCH*NX*DIMC;

    float *catln, *qkvb, *attno, *ln2o, *fc1o, *wrnd, *pO, *pL;
    cudaGetSymbolAddress((void**)&catln, g_catln);
    cudaGetSymbolAddress((void**)&qkvb,  g_qkv);
    cudaGetSymbolAddress((void**)&attno, g_attno);
    cudaGetSymbolAddress((void**)&ln2o,  g_ln2);
    cudaGetSymbolAddress((void**)&fc1o,  g_fc1);
    cudaGetSymbolAddress((void**)&wrnd,  g_wrnd);
    cudaGetSymbolAddress((void**)&pO,    g_pO);
    cudaGetSymbolAddress((void**)&pL,    g_pL);

    cudaFuncSetAttribute(attn_v2<false>, cudaFuncAttributeMaxDynamicSharedMemorySize, SMEM_ATTN);
    cudaFuncSetAttribute(attn_v2<true>,  cudaFuncAttributeMaxDynamicSharedMemorySize, SMEM_ATTN);

    // 0) pre-round weights to tf32
    round_weights<<<256, 256>>>(qkvw, projw, fc1w, fc2w, wrnd);
    // 1) LN1 over concat(x, y)
    ln_kernel<<<TTOK, 128>>>(x, y, n1w, n1b, catln);
    // 2) fused QKV GEMM
    gemm_wmma<0><<<dim3(QKVN/64, TTOK/128), 256>>>(catln, wrnd + OFF_QKVW, nullptr, qkvb,
        TTOK, QKVN, DIMC, nullptr, nullptr, nullptr, nullptr);
    // 3) x self-attention (128 q/CTA)
    attn_v2<false><<<dim3(NX/128, HEADS, BATCH), 256, SMEM_ATTN>>>(qkvb, attno, nullptr, nullptr, 0, NX);
    // 4) y cross-attention: split-K x4 + merge
    attn_v2<true><<<dim3(QBY*NSPLIT, HEADS, BATCH), 256, SMEM_ATTN>>>(qkvb, nullptr, pO, pL, NX, KSPLIT);
    merge_attn<<<dim3(QBY, HEADS, BATCH), 128>>>(pO, pL, attno);
    // 5) output projection + bias + input residual -> d_out
    gemm_wmma<1><<<dim3(DIMC/64, TTOK/128), 256>>>(attno, wrnd + OFF_PROJW, projb, nullptr,
        TTOK, DIMC, DIMC, x, y, outx, outy);
    // 6) LN2 over d_out
    ln_kernel<<<TTOK, 128>>>(outx, outy, n2w, n2b, ln2o);
    // 7) fc1 + bias + exact GELU
    gemm_wmma<2><<<dim3(HIDDEN/64, TTOK/128), 256>>>(ln2o, wrnd + OFF_FC1W, fc1bb, fc1o,
        TTOK, HIDDEN, DIMC, nullptr, nullptr, nullptr, nullptr);
    // 8) fc2 + bias + residual (in place on d_out)
    gemm_wmma<3><<<dim3(DIMC/64, TTOK/128), 256>>>(fc1o, wrnd + OFF_FC2W, fc2b, nullptr,
        TTOK, DIMC, HIDDEN, nullptr, nullptr, outx, outy);
}

// round 9
// speedup vs baseline: 1.4190x; 1.2906x over previous
#include <cuda_runtime.h>
#include <cuda_bf16.h>
#include <math.h>
#include <stdint.h>
#include <mma.h>

using namespace nvcuda;

// ---------------- problem constants ----------------
#define DIMC   384
#define HEADS  6
#define HD     64
#define HIDDEN 1536
#define BATCH  4
#define NX     2048
#define NY     256
#define MTOK   2304
#define TTOK   (BATCH*MTOK)          // 9216
#define QKVN   (3*DIMC)              // 1152
#define ATT_SCALE 0.125f
#define LN_EPS 1e-5f

#define ATS 68                       // fp32 S row stride (elements)
#define BTS 72                       // bf16 row stride (elements); 144B, 16B-multiple

// attention dynamic smem layout (bytes)
#define OFF_KB0 0
#define OFF_KB1 (OFF_KB0 + 64*BTS*2)       //  9216
#define OFF_VB0 (OFF_KB1 + 64*BTS*2)       // 18432
#define OFF_VB1 (OFF_VB0 + 64*BTS*2)       // 27648
#define OFF_SS  (OFF_VB1 + 64*BTS*2)       // 36864  (fp32 128*ATS)
#define OFF_PB  (OFF_SS  + 128*ATS*4)      // 71680  (bf16 128*BTS; also Q staging)
#define SMEM_ATTN (OFF_PB + 128*BTS*2)     // 90112 B -> 2 CTAs/SM

#define NSPLIT 4
#define KSPLIT (MTOK/NSPLIT)         // 576
#define QBY    (NY/128)              // 2

// weight scratch offsets (tf32-rounded weights)
#define OFF_QKVW 0
#define OFF_PROJW (QKVN*DIMC)
#define OFF_FC1W  (OFF_PROJW + DIMC*DIMC)
#define OFF_FC2W  (OFF_FC1W + HIDDEN*DIMC)
#define W_TOTAL   (OFF_FC2W + DIMC*HIDDEN)

// ---------------- scratch ----------------
__device__ float          g_catln[TTOK*DIMC];
__device__ __nv_bfloat16  g_qkvh [TTOK*QKVN];          // qkv in bf16 (attention input)
__device__ float          g_attno[TTOK*DIMC];
__device__ float          g_ln2  [TTOK*DIMC];
__device__ float          g_fc1  [TTOK*HIDDEN];
__device__ float          g_wrnd [W_TOTAL];
__device__ float          g_pO   [BATCH*HEADS*QBY*NSPLIT*128*64];
__device__ float          g_pL   [BATCH*HEADS*QBY*NSPLIT*128];

// ---------------- helpers ----------------
__device__ __forceinline__ float f2tf32f(float f) {
    uint32_t u; asm("cvt.rna.tf32.f32 %0, %1;" : "=r"(u) : "f"(f));
    return __uint_as_float(u);
}
__device__ __forceinline__ void cp16(void* smem, const void* gmem) {
    uint32_t s = (uint32_t)__cvta_generic_to_shared(smem);
    asm volatile("cp.async.cg.shared.global [%0], [%1], 16;" :: "r"(s), "l"(gmem));
}
#define CP_COMMIT() asm volatile("cp.async.commit_group;")
#define CP_WAIT0()  asm volatile("cp.async.wait_group 0;")

// ---------------- weight pre-rounding ----------------
__global__ void round_weights(const float* __restrict__ qkvw, const float* __restrict__ projw,
                              const float* __restrict__ fc1w, const float* __restrict__ fc2w,
                              float* __restrict__ dst)
{
    int stride = gridDim.x * blockDim.x;
    int i0 = blockIdx.x * blockDim.x + threadIdx.x;
    for (int i = i0; i < QKVN*DIMC;   i += stride) dst[OFF_QKVW + i]  = f2tf32f(qkvw[i]);
    for (int i = i0; i < DIMC*DIMC;   i += stride) dst[OFF_PROJW + i] = f2tf32f(projw[i]);
    for (int i = i0; i < HIDDEN*DIMC; i += stride) dst[OFF_FC1W + i]  = f2tf32f(fc1w[i]);
    for (int i = i0; i < DIMC*HIDDEN; i += stride) dst[OFF_FC2W + i]  = f2tf32f(fc2w[i]);
}

// ---------------- LayerNorm (stores tf32-rounded) ----------------
__global__ void __launch_bounds__(128) ln_kernel(
    const float* __restrict__ px, const float* __restrict__ py,
    const float* __restrict__ w,  const float* __restrict__ bsh,
    float* __restrict__ out)
{
    int t   = blockIdx.x;
    int bb  = t / MTOK;
    int pos = t - bb * MTOK;
    const float* src = (pos < NX)
        ? px + ((size_t)(bb*NX + pos)) * DIMC
        : py + ((size_t)(bb*NY + pos - NX)) * DIMC;

    int tid = threadIdx.x;
    float v0 = src[tid], v1 = src[tid+128], v2 = src[tid+256];
    float s  = v0 + v1 + v2;
    float sq = v0*v0 + v1*v1 + v2*v2;
    #pragma unroll
    for (int o = 16; o; o >>= 1) {
        s  += __shfl_xor_sync(0xffffffffu, s,  o);
        sq += __shfl_xor_sync(0xffffffffu, sq, o);
    }
    __shared__ float sm[4], sm2[4], stat[2];
    int wi = tid >> 5;
    if ((tid & 31) == 0) { sm[wi] = s; sm2[wi] = sq; }
    __syncthreads();
    if (tid == 0) {
        float S = sm[0]+sm[1]+sm[2]+sm[3];
        float Q = sm2[0]+sm2[1]+sm2[2]+sm2[3];
        float mean = S * (1.0f/DIMC);
        float var  = Q * (1.0f/DIMC) - mean*mean;
        stat[0] = mean;
        stat[1] = rsqrtf(var + LN_EPS);
    }
    __syncthreads();
    float mean = stat[0], inv = stat[1];
    float* op = out + (size_t)t * DIMC;
    op[tid]     = f2tf32f((v0-mean)*inv*w[tid]     + bsh[tid]);
    op[tid+128] = f2tf32f((v1-mean)*inv*w[tid+128] + bsh[tid+128]);
    op[tid+256] = f2tf32f((v2-mean)*inv*w[tid+256] + bsh[tid+256]);
}

// ---------------- per-element epilogue ----------------
// EPI 0: bf16 store (qkv for attention) | 1: +bias+input residual (proj, final)
// EPI 2: +bias+erf GELU tf32 (fc1) | 3: +bias+out residual (fc2, final)
template<int EPI>
__device__ __forceinline__ void epi_elem(int m, int n, float v, int N,
    const float* __restrict__ bias, float* __restrict__ C,
    const float* __restrict__ resx, const float* __restrict__ resy,
    float* __restrict__ outx, float* __restrict__ outy)
{
    if (EPI == 0) {
        ((__nv_bfloat16*)C)[(size_t)m*N + n] = __float2bfloat16(v);
        return;
    }
    float bv = bias[n];
    if (EPI == 2) {
        float x = v + bv;
        C[(size_t)m*N + n] = f2tf32f(0.5f * x * (1.0f + erff(x * 0.70710678118654752f)));
        return;
    }
    int bb  = m / MTOK;
    int pos = m - bb * MTOK;
    if (pos < NX) {
        size_t idx = ((size_t)(bb*NX + pos))*DIMC + n;
        float r = (EPI == 1) ? resx[idx] : outx[idx];
        outx[idx] = v + bv + r;
    } else {
        size_t idx = ((size_t)(bb*NY + pos - NX))*DIMC + n;
        float r = (EPI == 1) ? resy[idx] : outy[idx];
        outy[idx] = v + bv + r;
    }
}

// ---------------- staged wmma tf32 GEMM: C = A * W^T ----------------
template<int EPI>
__global__ void __launch_bounds__(256) gemm_wmma(
    const float* __restrict__ A, const float* __restrict__ W,
    const float* __restrict__ bias, float* __restrict__ C,
    int M, int N, int K,
    const float* __restrict__ resx, const float* __restrict__ resy,
    float* __restrict__ outx, float* __restrict__ outy)
{
    __shared__ __align__(16) float As[128*36];
    __shared__ __align__(16) float Ws[64*36];
    __shared__ __align__(16) float Ct[8][16*20];

    int tid = threadIdx.x;
    int w = tid >> 5, lane = tid & 31;
    int wm = w >> 1, wn = w & 1;
    int m0 = blockIdx.y << 7;
    int n0 = blockIdx.x << 6;

    wmma::fragment<wmma::accumulator, 16, 16, 8, float> acc[2][2];
    #pragma unroll
    for (int i = 0; i < 2; i++)
        #pragma unroll
        for (int j = 0; j < 2; j++) wmma::fill_fragment(acc[i][j], 0.0f);

    for (int k0 = 0; k0 < K; k0 += 32) {
        #pragma unroll
        for (int i = 0; i < 4; i++) {
            int idx = tid + i*256;
            int row = idx >> 3, c4 = (idx & 7) << 2;
            *(float4*)(As + row*36 + c4) = *(const float4*)(A + (size_t)(m0+row)*K + k0 + c4);
        }
        #pragma unroll
        for (int i = 0; i < 2; i++) {
            int idx = tid + i*256;
            int row = idx >> 3, c4 = (idx & 7) << 2;
            *(float4*)(Ws + row*36 + c4) = *(const float4*)(W + (size_t)(n0+row)*K + k0 + c4);
        }
        __syncthreads();

        #pragma unroll
        for (int ks = 0; ks < 4; ks++) {
            int kb = ks << 3;
            wmma::fragment<wmma::matrix_a, 16, 16, 8, wmma::precision::tf32, wmma::row_major> af[2];
            wmma::fragment<wmma::matrix_b, 16, 16, 8, wmma::precision::tf32, wmma::col_major> bf[2];
            wmma::load_matrix_sync(af[0], As + (wm*32     )*36 + kb, 36);
            wmma::load_matrix_sync(af[1], As + (wm*32 + 16)*36 + kb, 36);
            wmma::load_matrix_sync(bf[0], Ws + (wn*32     )*36 + kb, 36);
            wmma::load_matrix_sync(bf[1], Ws + (wn*32 + 16)*36 + kb, 36);
            #pragma unroll
            for (int i = 0; i < 2; i++)
                #pragma unroll
                for (int j = 0; j < 2; j++)
                    wmma::mma_sync(acc[i][j], af[i], bf[j], acc[i][j]);
        }
        __syncthreads();
    }

    #pragma unroll
    for (int i = 0; i < 2; i++) {
        #pragma unroll
        for (int j = 0; j < 2; j++) {
            wmma::store_matrix_sync(&Ct[w][0], acc[i][j], 20, wmma::mem_row_major);
            __syncwarp();
            int r  = lane >> 1;
            int cb = (lane & 1) << 3;
            int mg = m0 + wm*32 + i*16 + r;
            int ng = n0 + wn*32 + j*16 + cb;
            #pragma unroll
            for (int q = 0; q < 8; q++)
                epi_elem<EPI>(mg, ng + q, Ct[w][r*20 + cb + q], N, bias, C, resx, resy, outx, outy);
            __syncwarp();
        }
    }
}

// ---------------- attention v3: bf16 mma, no-max softmax, register O ----------------
// 128 q/block, 8 warps x 16 rows; cp.async double-buffered bf16 K/V tiles.
template<bool SPLIT>
__global__ void __launch_bounds__(256, 2) attn_v3(
    const __nv_bfloat16* __restrict__ qkvh, float* __restrict__ attno,
    float* __restrict__ pO, float* __restrict__ pL,
    int q_base, int klen)
{
    extern __shared__ __align__(16) char dsm[];
    __nv_bfloat16* Kb[2] = { (__nv_bfloat16*)(dsm + OFF_KB0), (__nv_bfloat16*)(dsm + OFF_KB1) };
    __nv_bfloat16* Vb[2] = { (__nv_bfloat16*)(dsm + OFF_VB0), (__nv_bfloat16*)(dsm + OFF_VB1) };
    float*         Ss    = (float*)(dsm + OFF_SS);
    __nv_bfloat16* Pb    = (__nv_bfloat16*)(dsm + OFF_PB);   // Q staging, then P

    int tid = threadIdx.x, w = tid >> 5, lane = tid & 31;
    int h = blockIdx.y, b = blockIdx.z;
    int qb, sp;
    if (SPLIT) { qb = blockIdx.x >> 2; sp = blockIdx.x & 3; }
    else       { qb = blockIdx.x;      sp = 0; }
    int q0   = q_base + (qb << 7);
    int koff = SPLIT ? sp * klen : 0;

    // stage Q (x ATT_SCALE, exact exponent shift in bf16) into Pb
    {
        __nv_bfloat162 sc2 = __float2bfloat162_rn(ATT_SCALE);
        #pragma unroll
        for (int i = 0; i < 4; i++) {
            int idx = tid + i*256;
            int row = idx >> 3, c8 = (idx & 7) << 3;
            const __nv_bfloat162* src = (const __nv_bfloat162*)
                (qkvh + ((size_t)(b*MTOK + q0 + row))*QKVN + h*HD + c8);
            __nv_bfloat162* dst = (__nv_bfloat162*)(Pb + row*BTS + c8);
            #pragma unroll
            for (int p = 0; p < 4; p++) dst[p] = __hmul2(src[p], sc2);
        }
    }
    __syncthreads();

    wmma::fragment<wmma::matrix_a, 16, 16, 16, __nv_bfloat16, wmma::row_major> qa[4];
    #pragma unroll
    for (int kk = 0; kk < 4; kk++)
        wmma::load_matrix_sync(qa[kk], Pb + (w*16)*BTS + kk*16, BTS);

    wmma::fragment<wmma::accumulator, 16, 16, 16, float> oacc[4];
    #pragma unroll
    for (int j = 0; j < 4; j++) wmma::fill_fragment(oacc[j], 0.0f);
    float lreg = 0.f;

    const __nv_bfloat16* kbase = qkvh + ((size_t)b*MTOK)*QKVN + DIMC   + h*HD;
    const __nv_bfloat16* vbase = qkvh + ((size_t)b*MTOK)*QKVN + 2*DIMC + h*HD;

    int T = klen >> 6;
    {   // stage tile 0 (64 rows x 128B for K and V; 1024 chunks / 256 thr = 4)
        #pragma unroll
        for (int i = 0; i < 2; i++) {
            int idx = tid + i*256;
            int row = idx >> 3, c8 = (idx & 7) << 3;
            cp16(Kb[0] + row*BTS + c8, kbase + (size_t)(koff+row)*QKVN + c8);
            cp16(Vb[0] + row*BTS + c8, vbase + (size_t)(koff+row)*QKVN + c8);
        }
        CP_COMMIT();
    }

    for (int t = 0; t < T; t++) {
        CP_WAIT0();
        __syncthreads();
        if (t + 1 < T) {
            int kt = koff + ((t+1) << 6);
            __nv_bfloat16* Kn = Kb[(t+1)&1];
            __nv_bfloat16* Vn = Vb[(t+1)&1];
            #pragma unroll
            for (int i = 0; i < 2; i++) {
                int idx = tid + i*256;
                int row = idx >> 3, c8 = (idx & 7) << 3;
                cp16(Kn + row*BTS + c8, kbase + (size_t)(kt+row)*QKVN + c8);
                cp16(Vn + row*BTS + c8, vbase + (size_t)(kt+row)*QKVN + c8);
            }
            CP_COMMIT();
        }
        __nv_bfloat16* Ks = Kb[t&1];
        __nv_bfloat16* Vs = Vb[t&1];

        // S = Q @ K^T -> Ss (own 16 rows)
        #pragma unroll
        for (int j = 0; j < 4; j++) {
            wmma::fragment<wmma::accumulator, 16, 16, 16, float> sacc;
            wmma::fill_fragment(sacc, 0.0f);
            #pragma unroll
            for (int kk = 0; kk < 4; kk++) {
                wmma::fragment<wmma::matrix_b, 16, 16, 16, __nv_bfloat16, wmma::col_major> kf;
                wmma::load_matrix_sync(kf, Ks + (j*16)*BTS + kk*16, BTS);
                wmma::mma_sync(sacc, qa[kk], kf, sacc);
            }
            wmma::store_matrix_sync(Ss + (w*16)*ATS + j*16, sacc, ATS, wmma::mem_row_major);
        }
        __syncwarp();

        // no-max softmax: P = exp(S) -> bf16 Pb, accumulate row sum
        {
            int r  = lane >> 1;
            int hf = lane & 1;
            const float* srow = Ss + (w*16 + r)*ATS + hf*32;
            __nv_bfloat16* prow = Pb + (w*16 + r)*BTS + hf*32;
            float ps = 0.f;
            #pragma unroll
            for (int c = 0; c < 32; c++) {
                float p = __expf(srow[c]);
                ps += p;
                prow[c] = __float2bfloat16(p);
            }
            lreg += ps;
        }
        __syncwarp();

        // O += P @ V (O in registers)
        wmma::fragment<wmma::matrix_a, 16, 16, 16, __nv_bfloat16, wmma::row_major> pa[4];
        #pragma unroll
        for (int kk = 0; kk < 4; kk++)
            wmma::load_matrix_sync(pa[kk], Pb + (w*16)*BTS + kk*16, BTS);
        #pragma unroll
        for (int j = 0; j < 4; j++) {
            #pragma unroll
            for (int kk = 0; kk < 4; kk++) {
                wmma::fragment<wmma::matrix_b, 16, 16, 16, __nv_bfloat16, wmma::row_major> vf;
                wmma::load_matrix_sync(vf, Vs + (kk*16)*BTS + j*16, BTS);
                wmma::mma_sync(oacc[j], pa[kk], vf, oacc[j]);
            }
        }
    }

    // dump O to own Ss rows, then write out
    #pragma unroll
    for (int j = 0; j < 4; j++)
        wmma::store_matrix_sync(Ss + (w*16)*ATS + j*16, oacc[j], ATS, wmma::mem_row_major);
    __syncwarp();

    float ltot = lreg + __shfl_xor_sync(0xffffffffu, lreg, 1);
    int r  = lane >> 1;
    int hf = lane & 1;
    int row = w*16 + r;
    const float* orow = Ss + row*ATS + hf*32;

    if (SPLIT) {
        int pidx = ((b*HEADS + h)*QBY + qb)*NSPLIT + sp;
        float* dst = pO + (size_t)pidx*(128*64) + row*64 + hf*32;
        #pragma unroll
        for (int c4 = 0; c4 < 8; c4++)
            *(float4*)(dst + c4*4) = *(const float4*)(orow + c4*4);
        if (hf == 0) pL[pidx*128 + row] = ltot;
    } else {
        float inv = 1.f / ltot;
        float* op = attno + ((size_t)(b*MTOK + q0 + row))*DIMC + h*HD + hf*32;
        #pragma unroll
        for (int c = 0; c < 32; c++) op[c] = f2tf32f(orow[c]*inv);
    }
}

// ---------------- merge split-K partials ----------------
__global__ void __launch_bounds__(128) merge_attn(
    const float* __restrict__ pO, const float* __restrict__ pL,
    float* __restrict__ attno)
{
    int qb = blockIdx.x, h = blockIdx.y, b = blockIdx.z;
    int r = threadIdx.x;
    int base = ((b*HEADS + h)*QBY + qb)*NSPLIT;

    float L = 0.f;
    #pragma unroll
    for (int s = 0; s < NSPLIT; s++) L += pL[(base+s)*128 + r];
    float inv = 1.f / L;

    int qi = NX + (qb << 7) + r;
    float* op = attno + ((size_t)(b*MTOK + qi))*DIMC + h*HD;
    #pragma unroll 4
    for (int c = 0; c < 64; c++) {
        float o = 0.f;
        #pragma unroll
        for (int s = 0; s < NSPLIT; s++)
            o += pO[(size_t)(base+s)*(128*64) + r*64 + c];
        op[c] = f2tf32f(o * inv);
    }
}

// ---------------- launch ----------------
extern "C" void kernel_launch(void* const* d_in, const int* in_sizes, int n_in,
                              void* d_out, int out_size)
{
    const float* x     = (const float*)d_in[0];
    const float* y     = (const float*)d_in[1];
    const float* n1w   = (const float*)d_in[2];
    const float* n1b   = (const float*)d_in[3];
    const float* n2w   = (const float*)d_in[4];
    const float* n2b   = (const float*)d_in[5];
    const float* qkvw  = (const float*)d_in[6];
    const float* projw = (const float*)d_in[7];
    const float* projb = (const float*)d_in[8];
    const float* fc1w  = (const float*)d_in[9];
    const float* fc1bb = (const float*)d_in[10];
    const float* fc2w  = (const float*)d_in[11];
    const float* fc2b  = (const float*)d_in[12];
    (void)in_sizes; (void)n_in; (void)out_size;

    float* outx = (float*)d_out;
    float* outy = outx + (size_t)BATCH*NX*DIMC;

    float *catln, *attno, *ln2o, *fc1o, *wrnd, *pO, *pL;
    __nv_bfloat16* qkvh;
    cudaGetSymbolAddress((void**)&catln, g_catln);
    cudaGetSymbolAddress((void**)&qkvh,  g_qkvh);
    cudaGetSymbolAddress((void**)&attno, g_attno);
    cudaGetSymbolAddress((void**)&ln2o,  g_ln2);
    cudaGetSymbolAddress((void**)&fc1o,  g_fc1);
    cudaGetSymbolAddress((void**)&wrnd,  g_wrnd);
    cudaGetSymbolAddress((void**)&pO,    g_pO);
    cudaGetSymbolAddress((void**)&pL,    g_pL);

    cudaFuncSetAttribute(attn_v3<false>, cudaFuncAttributeMaxDynamicSharedMemorySize, SMEM_ATTN);
    cudaFuncSetAttribute(attn_v3<true>,  cudaFuncAttributeMaxDynamicSharedMemorySize, SMEM_ATTN);

    // 0) pre-round weights to tf32
    round_weights<<<256, 256>>>(qkvw, projw, fc1w, fc2w, wrnd);
    // 1) LN1 over concat(x, y)
    ln_kernel<<<TTOK, 128>>>(x, y, n1w, n1b, catln);
    // 2) fused QKV GEMM (bf16 epilogue for attention)
    gemm_wmma<0><<<dim3(QKVN/64, TTOK/128), 256>>>(catln, wrnd + OFF_QKVW, nullptr, (float*)qkvh,
        TTOK, QKVN, DIMC, nullptr, nullptr, nullptr, nullptr);
    // 3) x self-attention (bf16, 128 q/CTA)
    attn_v3<false><<<dim3(NX/128, HEADS, BATCH), 256, SMEM_ATTN>>>(qkvh, attno, nullptr, nullptr, 0, NX);
    // 4) y cross-attention: split-K x4 + merge
    attn_v3<true><<<dim3(QBY*NSPLIT, HEADS, BATCH), 256, SMEM_ATTN>>>(qkvh, nullptr, pO, pL, NX, KSPLIT);
    merge_attn<<<dim3(QBY, HEADS, BATCH), 128>>>(pO, pL, attno);
    // 5) output projection + bias + input residual -> d_out
    gemm_wmma<1><<<dim3(DIMC/64, TTOK/128), 256>>>(attno, wrnd + OFF_PROJW, projb, nullptr,
        TTOK, DIMC, DIMC, x, y, outx, outy);
    // 6) LN2 over d_out
    ln_kernel<<<TTOK, 128>>>(outx, outy, n2w, n2b, ln2o);
    // 7) fc1 + bias + exact GELU
    gemm_wmma<2><<<dim3(HIDDEN/64, TTOK/128), 256>>>(ln2o, wrnd + OFF_FC1W, fc1bb, fc1o,
        TTOK, HIDDEN, DIMC, nullptr, nullptr, nullptr, nullptr);
    // 8) fc2 + bias + residual (in place on d_out)
    gemm_wmma<3><<<dim3(DIMC/64, TTOK/128), 256>>>(fc1o, wrnd + OFF_FC2W, fc2b, nullptr,
        TTOK, DIMC, HIDDEN, nullptr, nullptr, outx, outy);
}

// round 10
// speedup vs baseline: 1.9943x; 1.4054x over previous
#include <cuda_runtime.h>
#include <cuda_fp16.h>
#include <math.h>
#include <stdint.h>
#include <mma.h>

using namespace nvcuda;

// ---------------- problem constants ----------------
#define DIMC   384
#define HEADS  6
#define HD     64
#define HIDDEN 1536
#define BATCH  4
#define NX     2048
#define NY     256
#define MTOK   2304
#define TTOK   (BATCH*MTOK)          // 9216
#define QKVN   (3*DIMC)              // 1152
#define ATT_SCALE 0.125f
#define LN_EPS 1e-5f

#define ATS 68                       // fp32 S row stride (elements)
#define HTS 72                       // half row stride (elements); 144B

// attention dynamic smem layout (bytes)
#define OFF_KB0 0
#define OFF_KB1 (OFF_KB0 + 64*HTS*2)
#define OFF_VB0 (OFF_KB1 + 64*HTS*2)
#define OFF_VB1 (OFF_VB0 + 64*HTS*2)
#define OFF_SS  (OFF_VB1 + 64*HTS*2)       // fp32 128*ATS
#define OFF_PB  (OFF_SS  + 128*ATS*4)      // half 128*HTS (Q staging, then P)
#define SMEM_ATTN (OFF_PB + 128*HTS*2)     // 90112 B

// GEMM dynamic smem layout (half tiles, k-tile 64)
#define GA_BYTES (128*HTS*2)               // 18432
#define GW_BYTES (64*HTS*2)                //  9216
#define GOFF_A0  0
#define GOFF_A1  (GOFF_A0 + GA_BYTES)
#define GOFF_W0  (GOFF_A1 + GA_BYTES)
#define GOFF_W1  (GOFF_W0 + GW_BYTES)
#define GOFF_CT  (GOFF_W1 + GW_BYTES)      // 55296, fp32 8*320
#define SMEM_GEMM (GOFF_CT + 8*320*4)      // 65536 B

#define NSPLIT 4
#define KSPLIT (MTOK/NSPLIT)         // 576
#define QBY    (NY/128)              // 2

// weight scratch offsets (half weights)
#define OFF_QKVW 0
#define OFF_PROJW (QKVN*DIMC)
#define OFF_FC1W  (OFF_PROJW + DIMC*DIMC)
#define OFF_FC2W  (OFF_FC1W + HIDDEN*DIMC)
#define W_TOTAL   (OFF_FC2W + DIMC*HIDDEN)

// ---------------- scratch ----------------
__device__ __half g_catln[TTOK*DIMC];
__device__ __half g_qkvh [TTOK*QKVN];
__device__ __half g_attno[TTOK*DIMC];
__device__ __half g_ln2  [TTOK*DIMC];
__device__ __half g_fc1  [TTOK*HIDDEN];
__device__ __half g_wrnd [W_TOTAL];
__device__ float  g_pO   [BATCH*HEADS*QBY*NSPLIT*128*64];
__device__ float  g_pL   [BATCH*HEADS*QBY*NSPLIT*128];

// ---------------- helpers ----------------
__device__ __forceinline__ void cp16(void* smem, const void* gmem) {
    uint32_t s = (uint32_t)__cvta_generic_to_shared(smem);
    asm volatile("cp.async.cg.shared.global [%0], [%1], 16;" :: "r"(s), "l"(gmem));
}
#define CP_COMMIT() asm volatile("cp.async.commit_group;")
#define CP_WAIT0()  asm volatile("cp.async.wait_group 0;")

// ---------------- weight pre-rounding to fp16 ----------------
__global__ void round_weights(const float* __restrict__ qkvw, const float* __restrict__ projw,
                              const float* __restrict__ fc1w, const float* __restrict__ fc2w,
                              __half* __restrict__ dst)
{
    int stride = gridDim.x * blockDim.x;
    int i0 = blockIdx.x * blockDim.x + threadIdx.x;
    for (int i = i0; i < QKVN*DIMC;   i += stride) dst[OFF_QKVW + i]  = __float2half(qkvw[i]);
    for (int i = i0; i < DIMC*DIMC;   i += stride) dst[OFF_PROJW + i] = __float2half(projw[i]);
    for (int i = i0; i < HIDDEN*DIMC; i += stride) dst[OFF_FC1W + i]  = __float2half(fc1w[i]);
    for (int i = i0; i < DIMC*HIDDEN; i += stride) dst[OFF_FC2W + i]  = __float2half(fc2w[i]);
}

// ---------------- LayerNorm (fp32 in, fp16 out) ----------------
__global__ void __launch_bounds__(128) ln_kernel(
    const float* __restrict__ px, const float* __restrict__ py,
    const float* __restrict__ w,  const float* __restrict__ bsh,
    __half* __restrict__ out)
{
    int t   = blockIdx.x;
    int bb  = t / MTOK;
    int pos = t - bb * MTOK;
    const float* src = (pos < NX)
        ? px + ((size_t)(bb*NX + pos)) * DIMC
        : py + ((size_t)(bb*NY + pos - NX)) * DIMC;

    int tid = threadIdx.x;
    float v0 = src[tid], v1 = src[tid+128], v2 = src[tid+256];
    float s  = v0 + v1 + v2;
    float sq = v0*v0 + v1*v1 + v2*v2;
    #pragma unroll
    for (int o = 16; o; o >>= 1) {
        s  += __shfl_xor_sync(0xffffffffu, s,  o);
        sq += __shfl_xor_sync(0xffffffffu, sq, o);
    }
    __shared__ float sm[4], sm2[4], stat[2];
    int wi = tid >> 5;
    if ((tid & 31) == 0) { sm[wi] = s; sm2[wi] = sq; }
    __syncthreads();
    if (tid == 0) {
        float S = sm[0]+sm[1]+sm[2]+sm[3];
        float Q = sm2[0]+sm2[1]+sm2[2]+sm2[3];
        float mean = S * (1.0f/DIMC);
        float var  = Q * (1.0f/DIMC) - mean*mean;
        stat[0] = mean;
        stat[1] = rsqrtf(var + LN_EPS);
    }
    __syncthreads();
    float mean = stat[0], inv = stat[1];
    __half* op = out + (size_t)t * DIMC;
    op[tid]     = __float2half((v0-mean)*inv*w[tid]     + bsh[tid]);
    op[tid+128] = __float2half((v1-mean)*inv*w[tid+128] + bsh[tid+128]);
    op[tid+256] = __float2half((v2-mean)*inv*w[tid+256] + bsh[tid+256]);
}

// ---------------- per-element epilogue ----------------
// EPI 0: fp16 store (qkv) | 1: +bias+input residual fp32 (proj, final)
// EPI 2: +bias+erf GELU fp16 (fc1) | 3: +bias+out residual fp32 (fc2, final)
template<int EPI>
__device__ __forceinline__ void epi_elem(int m, int n, float v, int N,
    const float* __restrict__ bias, __half* __restrict__ C,
    const float* __restrict__ resx, const float* __restrict__ resy,
    float* __restrict__ outx, float* __restrict__ outy)
{
    if (EPI == 0) { C[(size_t)m*N + n] = __float2half(v); return; }
    float bv = bias[n];
    if (EPI == 2) {
        float x = v + bv;
        C[(size_t)m*N + n] = __float2half(0.5f * x * (1.0f + erff(x * 0.70710678118654752f)));
        return;
    }
    int bb  = m / MTOK;
    int pos = m - bb * MTOK;
    if (pos < NX) {
        size_t idx = ((size_t)(bb*NX + pos))*DIMC + n;
        float r = (EPI == 1) ? resx[idx] : outx[idx];
        outx[idx] = v + bv + r;
    } else {
        size_t idx = ((size_t)(bb*NY + pos - NX))*DIMC + n;
        float r = (EPI == 1) ? resy[idx] : outy[idx];
        outy[idx] = v + bv + r;
    }
}

// ---------------- fp16 wmma GEMM, cp.async double-buffered ----------------
// C[M,N] = A[M,K] * W[N,K]^T. Block 128x64, 8 warps (4x2), warp 32x32, k-tile 64.
template<int EPI>
__global__ void __launch_bounds__(256, 2) gemm_fp16(
    const __half* __restrict__ A, const __half* __restrict__ W,
    const float* __restrict__ bias, __half* __restrict__ C,
    int M, int N, int K,
    const float* __restrict__ resx, const float* __restrict__ resy,
    float* __restrict__ outx, float* __restrict__ outy)
{
    extern __shared__ __align__(16) char dsm[];
    __half* Ab[2] = { (__half*)(dsm + GOFF_A0), (__half*)(dsm + GOFF_A1) };
    __half* Wb[2] = { (__half*)(dsm + GOFF_W0), (__half*)(dsm + GOFF_W1) };
    float*  Ct    = (float*)(dsm + GOFF_CT);

    int tid = threadIdx.x;
    int w = tid >> 5, lane = tid & 31;
    int wm = w >> 1, wn = w & 1;
    int m0 = blockIdx.y << 7;
    int n0 = blockIdx.x << 6;

    wmma::fragment<wmma::accumulator, 16, 16, 16, float> acc[2][2];
    #pragma unroll
    for (int i = 0; i < 2; i++)
        #pragma unroll
        for (int j = 0; j < 2; j++) wmma::fill_fragment(acc[i][j], 0.0f);

    int T = K >> 6;
    // stage tile 0: A 128 rows x 8 chunks, W 64 rows x 8 chunks (16B = 8 halves)
    {
        #pragma unroll
        for (int i = 0; i < 4; i++) {
            int idx = tid + i*256;
            int row = idx >> 3, c8 = (idx & 7) << 3;
            cp16(Ab[0] + row*HTS + c8, A + (size_t)(m0+row)*K + c8);
        }
        #pragma unroll
        for (int i = 0; i < 2; i++) {
            int idx = tid + i*256;
            int row = idx >> 3, c8 = (idx & 7) << 3;
            cp16(Wb[0] + row*HTS + c8, W + (size_t)(n0+row)*K + c8);
        }
        CP_COMMIT();
    }

    for (int t = 0; t < T; t++) {
        CP_WAIT0();
        __syncthreads();
        if (t + 1 < T) {
            int k0 = (t+1) << 6;
            __half* An = Ab[(t+1)&1];
            __half* Wn = Wb[(t+1)&1];
            #pragma unroll
            for (int i = 0; i < 4; i++) {
                int idx = tid + i*256;
                int row = idx >> 3, c8 = (idx & 7) << 3;
                cp16(An + row*HTS + c8, A + (size_t)(m0+row)*K + k0 + c8);
            }
            #pragma unroll
            for (int i = 0; i < 2; i++) {
                int idx = tid + i*256;
                int row = idx >> 3, c8 = (idx & 7) << 3;
                cp16(Wn + row*HTS + c8, W + (size_t)(n0+row)*K + k0 + c8);
            }
            CP_COMMIT();
        }
        __half* Ac = Ab[t&1];
        __half* Wc = Wb[t&1];
        #pragma unroll
        for (int ks = 0; ks < 4; ks++) {
            int kb = ks << 4;
            wmma::fragment<wmma::matrix_a, 16, 16, 16, __half, wmma::row_major> af[2];
            wmma::fragment<wmma::matrix_b, 16, 16, 16, __half, wmma::col_major> bf[2];
            wmma::load_matrix_sync(af[0], Ac + (wm*32     )*HTS + kb, HTS);
            wmma::load_matrix_sync(af[1], Ac + (wm*32 + 16)*HTS + kb, HTS);
            wmma::load_matrix_sync(bf[0], Wc + (wn*32     )*HTS + kb, HTS);
            wmma::load_matrix_sync(bf[1], Wc + (wn*32 + 16)*HTS + kb, HTS);
            #pragma unroll
            for (int i = 0; i < 2; i++)
                #pragma unroll
                for (int j = 0; j < 2; j++)
                    wmma::mma_sync(acc[i][j], af[i], bf[j], acc[i][j]);
        }
        __syncthreads();
    }

    float* myCt = Ct + w*320;
    #pragma unroll
    for (int i = 0; i < 2; i++) {
        #pragma unroll
        for (int j = 0; j < 2; j++) {
            wmma::store_matrix_sync(myCt, acc[i][j], 20, wmma::mem_row_major);
            __syncwarp();
            int r  = lane >> 1;
            int cb = (lane & 1) << 3;
            int mg = m0 + wm*32 + i*16 + r;
            int ng = n0 + wn*32 + j*16 + cb;
            #pragma unroll
            for (int q = 0; q < 8; q++)
                epi_elem<EPI>(mg, ng + q, myCt[r*20 + cb + q], N, bias, C, resx, resy, outx, outy);
            __syncwarp();
        }
    }
}

// ---------------- attention: fp16 mma, no-max softmax, register O ----------------
template<bool SPLIT>
__global__ void __launch_bounds__(256, 2) attn_v4(
    const __half* __restrict__ qkvh, __half* __restrict__ attno,
    float* __restrict__ pO, float* __restrict__ pL,
    int q_base, int klen)
{
    extern __shared__ __align__(16) char dsm[];
    __half* Kb[2] = { (__half*)(dsm + OFF_KB0), (__half*)(dsm + OFF_KB1) };
    __half* Vb[2] = { (__half*)(dsm + OFF_VB0), (__half*)(dsm + OFF_VB1) };
    float*  Ss    = (float*)(dsm + OFF_SS);
    __half* Pb    = (__half*)(dsm + OFF_PB);

    int tid = threadIdx.x, w = tid >> 5, lane = tid & 31;
    int h = blockIdx.y, b = blockIdx.z;
    int qb, sp;
    if (SPLIT) { qb = blockIdx.x >> 2; sp = blockIdx.x & 3; }
    else       { qb = blockIdx.x;      sp = 0; }
    int q0   = q_base + (qb << 7);
    int koff = SPLIT ? sp * klen : 0;

    // stage Q (x ATT_SCALE)
    {
        __half2 sc2 = __float2half2_rn(ATT_SCALE);
        #pragma unroll
        for (int i = 0; i < 4; i++) {
            int idx = tid + i*256;
            int row = idx >> 3, c8 = (idx & 7) << 3;
            const __half2* src = (const __half2*)
                (qkvh + ((size_t)(b*MTOK + q0 + row))*QKVN + h*HD + c8);
            __half2* dst = (__half2*)(Pb + row*HTS + c8);
            #pragma unroll
            for (int p = 0; p < 4; p++) dst[p] = __hmul2(src[p], sc2);
        }
    }
    __syncthreads();

    wmma::fragment<wmma::matrix_a, 16, 16, 16, __half, wmma::row_major> qa[4];
    #pragma unroll
    for (int kk = 0; kk < 4; kk++)
        wmma::load_matrix_sync(qa[kk], Pb + (w*16)*HTS + kk*16, HTS);

    wmma::fragment<wmma::accumulator, 16, 16, 16, float> oacc[4];
    #pragma unroll
    for (int j = 0; j < 4; j++) wmma::fill_fragment(oacc[j], 0.0f);
    float lreg = 0.f;

    const __half* kbase = qkvh + ((size_t)b*MTOK)*QKVN + DIMC   + h*HD;
    const __half* vbase = qkvh + ((size_t)b*MTOK)*QKVN + 2*DIMC + h*HD;

    int T = klen >> 6;
    {
        #pragma unroll
        for (int i = 0; i < 2; i++) {
            int idx = tid + i*256;
            int row = idx >> 3, c8 = (idx & 7) << 3;
            cp16(Kb[0] + row*HTS + c8, kbase + (size_t)(koff+row)*QKVN + c8);
            cp16(Vb[0] + row*HTS + c8, vbase + (size_t)(koff+row)*QKVN + c8);
        }
        CP_COMMIT();
    }

    for (int t = 0; t < T; t++) {
        CP_WAIT0();
        __syncthreads();
        if (t + 1 < T) {
            int kt = koff + ((t+1) << 6);
            __half* Kn = Kb[(t+1)&1];
            __half* Vn = Vb[(t+1)&1];
            #pragma unroll
            for (int i = 0; i < 2; i++) {
                int idx = tid + i*256;
                int row = idx >> 3, c8 = (idx & 7) << 3;
                cp16(Kn + row*HTS + c8, kbase + (size_t)(kt+row)*QKVN + c8);
                cp16(Vn + row*HTS + c8, vbase + (size_t)(kt+row)*QKVN + c8);
            }
            CP_COMMIT();
        }
        __half* Ks = Kb[t&1];
        __half* Vs = Vb[t&1];

        // S = Q @ K^T
        #pragma unroll
        for (int j = 0; j < 4; j++) {
            wmma::fragment<wmma::accumulator, 16, 16, 16, float> sacc;
            wmma::fill_fragment(sacc, 0.0f);
            #pragma unroll
            for (int kk = 0; kk < 4; kk++) {
                wmma::fragment<wmma::matrix_b, 16, 16, 16, __half, wmma::col_major> kf;
                wmma::load_matrix_sync(kf, Ks + (j*16)*HTS + kk*16, HTS);
                wmma::mma_sync(sacc, qa[kk], kf, sacc);
            }
            wmma::store_matrix_sync(Ss + (w*16)*ATS + j*16, sacc, ATS, wmma::mem_row_major);
        }
        __syncwarp();

        // no-max softmax: P = exp(S) -> fp16 Pb, accumulate row sum
        {
            int r  = lane >> 1;
            int hf = lane & 1;
            const float* srow = Ss + (w*16 + r)*ATS + hf*32;
            __half* prow = Pb + (w*16 + r)*HTS + hf*32;
            float ps = 0.f;
            #pragma unroll
            for (int c = 0; c < 32; c++) {
                float p = __expf(srow[c]);
                ps += p;
                prow[c] = __float2half(p);
            }
            lreg += ps;
        }
        __syncwarp();

        // O += P @ V
        wmma::fragment<wmma::matrix_a, 16, 16, 16, __half, wmma::row_major> pa[4];
        #pragma unroll
        for (int kk = 0; kk < 4; kk++)
            wmma::load_matrix_sync(pa[kk], Pb + (w*16)*HTS + kk*16, HTS);
        #pragma unroll
        for (int j = 0; j < 4; j++) {
            #pragma unroll
            for (int kk = 0; kk < 4; kk++) {
                wmma::fragment<wmma::matrix_b, 16, 16, 16, __half, wmma::row_major> vf;
                wmma::load_matrix_sync(vf, Vs + (kk*16)*HTS + j*16, HTS);
                wmma::mma_sync(oacc[j], pa[kk], vf, oacc[j]);
            }
        }
    }

    #pragma unroll
    for (int j = 0; j < 4; j++)
        wmma::store_matrix_sync(Ss + (w*16)*ATS + j*16, oacc[j], ATS, wmma::mem_row_major);
    __syncwarp();

    float ltot = lreg + __shfl_xor_sync(0xffffffffu, lreg, 1);
    int r  = lane >> 1;
    int hf = lane & 1;
    int row = w*16 + r;
    const float* orow = Ss + row*ATS + hf*32;

    if (SPLIT) {
        int pidx = ((b*HEADS + h)*QBY + qb)*NSPLIT + sp;
        float* dst = pO + (size_t)pidx*(128*64) + row*64 + hf*32;
        #pragma unroll
        for (int c4 = 0; c4 < 8; c4++)
            *(float4*)(dst + c4*4) = *(const float4*)(orow + c4*4);
        if (hf == 0) pL[pidx*128 + row] = ltot;
    } else {
        float inv = 1.f / ltot;
        __half* op = attno + ((size_t)(b*MTOK + q0 + row))*DIMC + h*HD + hf*32;
        #pragma unroll
        for (int c = 0; c < 32; c++) op[c] = __float2half(orow[c]*inv);
    }
}

// ---------------- merge split-K partials ----------------
__global__ void __launch_bounds__(128) merge_attn(
    const float* __restrict__ pO, const float* __restrict__ pL,
    __half* __restrict__ attno)
{
    int qb = blockIdx.x, h = blockIdx.y, b = blockIdx.z;
    int r = threadIdx.x;
    int base = ((b*HEADS + h)*QBY + qb)*NSPLIT;

    float L = 0.f;
    #pragma unroll
    for (int s = 0; s < NSPLIT; s++) L += pL[(base+s)*128 + r];
    float inv = 1.f / L;

    int qi = NX + (qb << 7) + r;
    __half* op = attno + ((size_t)(b*MTOK + qi))*DIMC + h*HD;
    #pragma unroll 4
    for (int c = 0; c < 64; c++) {
        float o = 0.f;
        #pragma unroll
        for (int s = 0; s < NSPLIT; s++)
            o += pO[(size_t)(base+s)*(128*64) + r*64 + c];
        op[c] = __float2half(o * inv);
    }
}

// ---------------- launch ----------------
extern "C" void kernel_launch(void* const* d_in, const int* in_sizes, int n_in,
                              void* d_out, int out_size)
{
    const float* x     = (const float*)d_in[0];
    const float* y     = (const float*)d_in[1];
    const float* n1w   = (const float*)d_in[2];
    const float* n1b   = (const float*)d_in[3];
    const float* n2w   = (const float*)d_in[4];
    const float* n2b   = (const float*)d_in[5];
    const float* qkvw  = (const float*)d_in[6];
    const float* projw = (const float*)d_in[7];
    const float* projb = (const float*)d_in[8];
    const float* fc1w  = (const float*)d_in[9];
    const float* fc1bb = (const float*)d_in[10];
    const float* fc2w  = (const float*)d_in[11];
    const float* fc2b  = (const float*)d_in[12];
    (void)in_sizes; (void)n_in; (void)out_size;

    float* outx = (float*)d_out;
    float* outy = outx + (size_t)BATCH*NX*DIMC;

    __half *catln, *qkvh, *attno, *ln2o, *fc1o, *wrnd;
    float *pO, *pL;
    cudaGetSymbolAddress((void**)&catln, g_catln);
    cudaGetSymbolAddress((void**)&qkvh,  g_qkvh);
    cudaGetSymbolAddress((void**)&attno, g_attno);
    cudaGetSymbolAddress((void**)&ln2o,  g_ln2);
    cudaGetSymbolAddress((void**)&fc1o,  g_fc1);
    cudaGetSymbolAddress((void**)&wrnd,  g_wrnd);
    cudaGetSymbolAddress((void**)&pO,    g_pO);
    cudaGetSymbolAddress((void**)&pL,    g_pL);

    cudaFuncSetAttribute(gemm_fp16<0>, cudaFuncAttributeMaxDynamicSharedMemorySize, SMEM_GEMM);
    cudaFuncSetAttribute(gemm_fp16<1>, cudaFuncAttributeMaxDynamicSharedMemorySize, SMEM_GEMM);
    cudaFuncSetAttribute(gemm_fp16<2>, cudaFuncAttributeMaxDynamicSharedMemorySize, SMEM_GEMM);
    cudaFuncSetAttribute(gemm_fp16<3>, cudaFuncAttributeMaxDynamicSharedMemorySize, SMEM_GEMM);
    cudaFuncSetAttribute(attn_v4<false>, cudaFuncAttributeMaxDynamicSharedMemorySize, SMEM_ATTN);
    cudaFuncSetAttribute(attn_v4<true>,  cudaFuncAttributeMaxDynamicSharedMemorySize, SMEM_ATTN);

    // 0) pre-round weights to fp16
    round_weights<<<256, 256>>>(qkvw, projw, fc1w, fc2w, wrnd);
    // 1) LN1 over concat(x, y)
    ln_kernel<<<TTOK, 128>>>(x, y, n1w, n1b, catln);
    // 2) fused QKV GEMM (fp16)
    gemm_fp16<0><<<dim3(QKVN/64, TTOK/128), 256, SMEM_GEMM>>>(catln, wrnd + OFF_QKVW, nullptr, qkvh,
        TTOK, QKVN, DIMC, nullptr, nullptr, nullptr, nullptr);
    // 3) x self-attention
    attn_v4<false><<<dim3(NX/128, HEADS, BATCH), 256, SMEM_ATTN>>>(qkvh, attno, nullptr, nullptr, 0, NX);
    // 4) y cross-attention: split-K x4 + merge
    attn_v4<true><<<dim3(QBY*NSPLIT, HEADS, BATCH), 256, SMEM_ATTN>>>(qkvh, nullptr, pO, pL, NX, KSPLIT);
    merge_attn<<<dim3(QBY, HEADS, BATCH), 128>>>(pO, pL, attno);
    // 5) output projection + bias + input residual -> d_out
    gemm_fp16<1><<<dim3(DIMC/64, TTOK/128), 256, SMEM_GEMM>>>(attno, wrnd + OFF_PROJW, projb, nullptr,
        TTOK, DIMC, DIMC, x, y, outx, outy);
    // 6) LN2 over d_out
    ln_kernel<<<TTOK, 128>>>(outx, outy, n2w, n2b, ln2o);
    // 7) fc1 + bias + exact GELU
    gemm_fp16<2><<<dim3(HIDDEN/64, TTOK/128), 256, SMEM_GEMM>>>(ln2o, wrnd + OFF_FC1W, fc1bb, fc1o,
        TTOK, HIDDEN, DIMC, nullptr, nullptr, nullptr, nullptr);
    // 8) fc2 + bias + residual (in place on d_out)
    gemm_fp16<3><<<dim3(DIMC/64, TTOK/128), 256, SMEM_GEMM>>>(fc1o, wrnd + OFF_FC2W, fc2b, nullptr,
        TTOK, DIMC, HIDDEN, nullptr, nullptr, outx, outy);
}

// round 11
// speedup vs baseline: 2.7879x; 1.3980x over previous
#include <cuda_runtime.h>
#include <cuda_fp16.h>
#include <math.h>
#include <stdint.h>
#include <mma.h>

using namespace nvcuda;

// ---------------- problem constants ----------------
#define DIMC   384
#define HEADS  6
#define HD     64
#define HIDDEN 1536
#define BATCH  4
#define NX     2048
#define NY     256
#define MTOK   2304
#define TTOK   (BATCH*MTOK)          // 9216
#define QKVN   (3*DIMC)              // 1152
#define ATT_SCALE 0.125f
#define LN_EPS 1e-5f

#define HTS 72                       // half row stride (elements); 144B

// attention smem: K/V double buffers only
#define SMEM_ATTN5 (4*64*HTS*2)      // 36,864 B

// GEMM dynamic smem layout (half tiles, k-tile 64)
#define GA_BYTES (128*HTS*2)
#define GW_BYTES (64*HTS*2)
#define GOFF_A0  0
#define GOFF_A1  (GOFF_A0 + GA_BYTES)
#define GOFF_W0  (GOFF_A1 + GA_BYTES)
#define GOFF_W1  (GOFF_W0 + GW_BYTES)
#define GOFF_CT  (GOFF_W1 + GW_BYTES)
#define SMEM_GEMM (GOFF_CT + 8*320*4)      // 65,536 B

#define NSPLIT 4
#define KSPLIT (MTOK/NSPLIT)         // 576
#define QBY    (NY/128)              // 2

// weight scratch offsets (half weights)
#define OFF_QKVW 0
#define OFF_PROJW (QKVN*DIMC)
#define OFF_FC1W  (OFF_PROJW + DIMC*DIMC)
#define OFF_FC2W  (OFF_FC1W + HIDDEN*DIMC)
#define W_TOTAL   (OFF_FC2W + DIMC*HIDDEN)

// ---------------- scratch ----------------
__device__ __half g_catln[TTOK*DIMC];
__device__ __half g_qkvh [TTOK*QKVN];
__device__ __half g_attno[TTOK*DIMC];
__device__ __half g_ln2  [TTOK*DIMC];
__device__ __half g_fc1  [TTOK*HIDDEN];
__device__ __half g_wrnd [W_TOTAL];
__device__ float  g_pO   [BATCH*HEADS*QBY*NSPLIT*128*64];
__device__ float  g_pL   [BATCH*HEADS*QBY*NSPLIT*128];

// ---------------- helpers ----------------
__device__ __forceinline__ void cp16(void* smem, const void* gmem) {
    uint32_t s = (uint32_t)__cvta_generic_to_shared(smem);
    asm volatile("cp.async.cg.shared.global [%0], [%1], 16;" :: "r"(s), "l"(gmem));
}
#define CP_COMMIT() asm volatile("cp.async.commit_group;")
#define CP_WAIT0()  asm volatile("cp.async.wait_group 0;")

__device__ __forceinline__ void mma16816(float* c, const uint32_t* a, uint32_t b0, uint32_t b1) {
    asm volatile(
        "mma.sync.aligned.m16n8k16.row.col.f32.f16.f16.f32 "
        "{%0,%1,%2,%3},{%4,%5,%6,%7},{%8,%9},{%0,%1,%2,%3};"
        : "+f"(c[0]), "+f"(c[1]), "+f"(c[2]), "+f"(c[3])
        : "r"(a[0]), "r"(a[1]), "r"(a[2]), "r"(a[3]), "r"(b0), "r"(b1));
}
__device__ __forceinline__ uint32_t pack_h2(float x, float y) {
    __half2 h = __floats2half2_rn(x, y);
    return *(uint32_t*)&h;
}

// ---------------- weight pre-rounding to fp16 ----------------
__global__ void round_weights(const float* __restrict__ qkvw, const float* __restrict__ projw,
                              const float* __restrict__ fc1w, const float* __restrict__ fc2w,
                              __half* __restrict__ dst)
{
    int stride = gridDim.x * blockDim.x;
    int i0 = blockIdx.x * blockDim.x + threadIdx.x;
    for (int i = i0; i < QKVN*DIMC;   i += stride) dst[OFF_QKVW + i]  = __float2half(qkvw[i]);
    for (int i = i0; i < DIMC*DIMC;   i += stride) dst[OFF_PROJW + i] = __float2half(projw[i]);
    for (int i = i0; i < HIDDEN*DIMC; i += stride) dst[OFF_FC1W + i]  = __float2half(fc1w[i]);
    for (int i = i0; i < DIMC*HIDDEN; i += stride) dst[OFF_FC2W + i]  = __float2half(fc2w[i]);
}

// ---------------- LayerNorm: 1 warp per token, 8 tokens per block ----------------
__global__ void __launch_bounds__(256) ln_fast(
    const float* __restrict__ px, const float* __restrict__ py,
    const float* __restrict__ w,  const float* __restrict__ bsh,
    __half* __restrict__ out)
{
    int wi = threadIdx.x >> 5, lane = threadIdx.x & 31;
    int t  = blockIdx.x*8 + wi;
    int bb = t / MTOK, pos = t - bb*MTOK;
    const float* src = (pos < NX)
        ? px + (size_t)(bb*NX + pos)*DIMC
        : py + (size_t)(bb*NY + pos - NX)*DIMC;

    float4 v[3];
    float s = 0.f, sq = 0.f;
    #pragma unroll
    for (int i = 0; i < 3; i++) {
        v[i] = ((const float4*)src)[lane + 32*i];
        s  += v[i].x + v[i].y + v[i].z + v[i].w;
        sq += v[i].x*v[i].x + v[i].y*v[i].y + v[i].z*v[i].z + v[i].w*v[i].w;
    }
    #pragma unroll
    for (int o = 16; o; o >>= 1) {
        s  += __shfl_xor_sync(0xffffffffu, s,  o);
        sq += __shfl_xor_sync(0xffffffffu, sq, o);
    }
    float mean = s * (1.0f/DIMC);
    float inv  = rsqrtf(sq * (1.0f/DIMC) - mean*mean + LN_EPS);

    uint32_t* op = (uint32_t*)(out + (size_t)t*DIMC);
    #pragma unroll
    for (int i = 0; i < 3; i++) {
        int idx4 = lane + 32*i;
        float4 ww = ((const float4*)w)[idx4];
        float4 bb4 = ((const float4*)bsh)[idx4];
        op[2*idx4]   = pack_h2((v[i].x-mean)*inv*ww.x + bb4.x, (v[i].y-mean)*inv*ww.y + bb4.y);
        op[2*idx4+1] = pack_h2((v[i].z-mean)*inv*ww.z + bb4.z, (v[i].w-mean)*inv*ww.w + bb4.w);
    }
}

// ---------------- per-element epilogue ----------------
template<int EPI>
__device__ __forceinline__ void epi_elem(int m, int n, float v, int N,
    const float* __restrict__ bias, __half* __restrict__ C,
    const float* __restrict__ resx, const float* __restrict__ resy,
    float* __restrict__ outx, float* __restrict__ outy)
{
    if (EPI == 0) { C[(size_t)m*N + n] = __float2half(v); return; }
    float bv = bias[n];
    if (EPI == 2) {
        float x = v + bv;
        C[(size_t)m*N + n] = __float2half(0.5f * x * (1.0f + erff(x * 0.70710678118654752f)));
        return;
    }
    int bb  = m / MTOK;
    int pos = m - bb * MTOK;
    if (pos < NX) {
        size_t idx = ((size_t)(bb*NX + pos))*DIMC + n;
        float r = (EPI == 1) ? resx[idx] : outx[idx];
        outx[idx] = v + bv + r;
    } else {
        size_t idx = ((size_t)(bb*NY + pos - NX))*DIMC + n;
        float r = (EPI == 1) ? resy[idx] : outy[idx];
        outy[idx] = v + bv + r;
    }
}

// ---------------- fp16 wmma GEMM, cp.async double-buffered (R10-proven) ----------------
template<int EPI>
__global__ void __launch_bounds__(256, 2) gemm_fp16(
    const __half* __restrict__ A, const __half* __restrict__ W,
    const float* __restrict__ bias, __half* __restrict__ C,
    int M, int N, int K,
    const float* __restrict__ resx, const float* __restrict__ resy,
    float* __restrict__ outx, float* __restrict__ outy)
{
    extern __shared__ __align__(16) char dsm[];
    __half* Ab[2] = { (__half*)(dsm + GOFF_A0), (__half*)(dsm + GOFF_A1) };
    __half* Wb[2] = { (__half*)(dsm + GOFF_W0), (__half*)(dsm + GOFF_W1) };
    float*  Ct    = (float*)(dsm + GOFF_CT);

    int tid = threadIdx.x;
    int w = tid >> 5, lane = tid & 31;
    int wm = w >> 1, wn = w & 1;
    int m0 = blockIdx.y << 7;
    int n0 = blockIdx.x << 6;

    wmma::fragment<wmma::accumulator, 16, 16, 16, float> acc[2][2];
    #pragma unroll
    for (int i = 0; i < 2; i++)
        #pragma unroll
        for (int j = 0; j < 2; j++) wmma::fill_fragment(acc[i][j], 0.0f);

    int T = K >> 6;
    {
        #pragma unroll
        for (int i = 0; i < 4; i++) {
            int idx = tid + i*256;
            int row = idx >> 3, c8 = (idx & 7) << 3;
            cp16(Ab[0] + row*HTS + c8, A + (size_t)(m0+row)*K + c8);
        }
        #pragma unroll
        for (int i = 0; i < 2; i++) {
            int idx = tid + i*256;
            int row = idx >> 3, c8 = (idx & 7) << 3;
            cp16(Wb[0] + row*HTS + c8, W + (size_t)(n0+row)*K + c8);
        }
        CP_COMMIT();
    }

    for (int t = 0; t < T; t++) {
        CP_WAIT0();
        __syncthreads();
        if (t + 1 < T) {
            int k0 = (t+1) << 6;
            __half* An = Ab[(t+1)&1];
            __half* Wn = Wb[(t+1)&1];
            #pragma unroll
            for (int i = 0; i < 4; i++) {
                int idx = tid + i*256;
                int row = idx >> 3, c8 = (idx & 7) << 3;
                cp16(An + row*HTS + c8, A + (size_t)(m0+row)*K + k0 + c8);
            }
            #pragma unroll
            for (int i = 0; i < 2; i++) {
                int idx = tid + i*256;
                int row = idx >> 3, c8 = (idx & 7) << 3;
                cp16(Wn + row*HTS + c8, W + (size_t)(n0+row)*K + k0 + c8);
            }
            CP_COMMIT();
        }
        __half* Ac = Ab[t&1];
        __half* Wc = Wb[t&1];
        #pragma unroll
        for (int ks = 0; ks < 4; ks++) {
            int kb = ks << 4;
            wmma::fragment<wmma::matrix_a, 16, 16, 16, __half, wmma::row_major> af[2];
            wmma::fragment<wmma::matrix_b, 16, 16, 16, __half, wmma::col_major> bf[2];
            wmma::load_matrix_sync(af[0], Ac + (wm*32     )*HTS + kb, HTS);
            wmma::load_matrix_sync(af[1], Ac + (wm*32 + 16)*HTS + kb, HTS);
            wmma::load_matrix_sync(bf[0], Wc + (wn*32     )*HTS + kb, HTS);
            wmma::load_matrix_sync(bf[1], Wc + (wn*32 + 16)*HTS + kb, HTS);
            #pragma unroll
            for (int i = 0; i < 2; i++)
                #pragma unroll
                for (int j = 0; j < 2; j++)
                    wmma::mma_sync(acc[i][j], af[i], bf[j], acc[i][j]);
        }
        __syncthreads();
    }

    float* myCt = Ct + w*320;
    #pragma unroll
    for (int i = 0; i < 2; i++) {
        #pragma unroll
        for (int j = 0; j < 2; j++) {
            wmma::store_matrix_sync(myCt, acc[i][j], 20, wmma::mem_row_major);
            __syncwarp();
            int r  = lane >> 1;
            int cb = (lane & 1) << 3;
            int mg = m0 + wm*32 + i*16 + r;
            int ng = n0 + wn*32 + j*16 + cb;
            #pragma unroll
            for (int q = 0; q < 8; q++)
                epi_elem<EPI>(mg, ng + q, myCt[r*20 + cb + q], N, bias, C, resx, resy, outx, outy);
            __syncwarp();
        }
    }
}

// ---------------- attention v5: raw PTX mma, register-resident S/P/O ----------------
// 128 q/block, 8 warps x 16 rows. Smem: K/V double buffers only.
// No-max softmax; P built in registers from S accumulator fragments (layout identity).
template<bool SPLIT>
__global__ void __launch_bounds__(256, 2) attn_v5(
    const __half* __restrict__ qkvh, __half* __restrict__ attno,
    float* __restrict__ pO, float* __restrict__ pL,
    int q_base, int klen)
{
    extern __shared__ __align__(16) char dsm[];
    __half* Kb[2] = { (__half*)(dsm),               (__half*)(dsm + 64*HTS*2)   };
    __half* Vb[2] = { (__half*)(dsm + 2*64*HTS*2),  (__half*)(dsm + 3*64*HTS*2) };

    int tid = threadIdx.x, w = tid >> 5, lane = tid & 31;
    int g = lane >> 2, t = lane & 3;
    int h = blockIdx.y, b = blockIdx.z;
    int qb, sp;
    if (SPLIT) { qb = blockIdx.x >> 2; sp = blockIdx.x & 3; }
    else       { qb = blockIdx.x;      sp = 0; }
    int q0   = q_base + (qb << 7);
    int koff = SPLIT ? sp * klen : 0;

    // Q fragments straight from global (unscaled; 0.125 applied post-mma in fp32)
    uint32_t qa[4][4];
    {
        const __half* qrow0 = qkvh + (size_t)(b*MTOK + q0 + w*16 + g)*QKVN + h*HD;
        const __half* qrow1 = qrow0 + 8*QKVN;
        #pragma unroll
        for (int c = 0; c < 4; c++) {
            qa[c][0] = *(const uint32_t*)(qrow0 + 16*c     + 2*t);
            qa[c][1] = *(const uint32_t*)(qrow1 + 16*c     + 2*t);
            qa[c][2] = *(const uint32_t*)(qrow0 + 16*c + 8 + 2*t);
            qa[c][3] = *(const uint32_t*)(qrow1 + 16*c + 8 + 2*t);
        }
    }

    float oac[8][4];
    #pragma unroll
    for (int j = 0; j < 8; j++)
        #pragma unroll
        for (int c = 0; c < 4; c++) oac[j][c] = 0.f;
    float rs0 = 0.f, rs1 = 0.f;

    const __half* kbase = qkvh + ((size_t)b*MTOK)*QKVN + DIMC   + h*HD;
    const __half* vbase = qkvh + ((size_t)b*MTOK)*QKVN + 2*DIMC + h*HD;

    int T = klen >> 6;
    {   // stage tile 0
        #pragma unroll
        for (int i = 0; i < 2; i++) {
            int idx = tid + i*256;
            int row = idx >> 3, c8 = (idx & 7) << 3;
            cp16(Kb[0] + row*HTS + c8, kbase + (size_t)(koff+row)*QKVN + c8);
            cp16(Vb[0] + row*HTS + c8, vbase + (size_t)(koff+row)*QKVN + c8);
        }
        CP_COMMIT();
    }

    for (int it = 0; it < T; it++) {
        CP_WAIT0();
        __syncthreads();
        if (it + 1 < T) {
            int kt = koff + ((it+1) << 6);
            __half* Kn = Kb[(it+1)&1];
            __half* Vn = Vb[(it+1)&1];
            #pragma unroll
            for (int i = 0; i < 2; i++) {
                int idx = tid + i*256;
                int row = idx >> 3, c8 = (idx & 7) << 3;
                cp16(Kn + row*HTS + c8, kbase + (size_t)(kt+row)*QKVN + c8);
                cp16(Vn + row*HTS + c8, vbase + (size_t)(kt+row)*QKVN + c8);
            }
            CP_COMMIT();
        }
        const uint32_t* Ku = (const uint32_t*)Kb[it&1];   // row stride 36 u32
        __half* Vs = Vb[it&1];

        // S = Q @ K^T per n8 tile j; exp in-register; pack P fragments
        uint32_t ph[8][2];
        #pragma unroll
        for (int j = 0; j < 8; j++) {
            float sc[4] = {0.f, 0.f, 0.f, 0.f};
            int krow = (8*j + g)*36 + t;
            #pragma unroll
            for (int c = 0; c < 4; c++)
                mma16816(sc, qa[c], Ku[krow + 8*c], Ku[krow + 8*c + 4]);
            float e0 = __expf(sc[0]*ATT_SCALE);
            float e1 = __expf(sc[1]*ATT_SCALE);
            float e2 = __expf(sc[2]*ATT_SCALE);
            float e3 = __expf(sc[3]*ATT_SCALE);
            rs0 += e0 + e1;
            rs1 += e2 + e3;
            ph[j][0] = pack_h2(e0, e1);
            ph[j][1] = pack_h2(e2, e3);
        }

        // O += P @ V : A-frags from ph (layout identity), B-frags via ldmatrix.x4.trans
        #pragma unroll
        for (int kc = 0; kc < 4; kc++) {
            uint32_t af[4] = { ph[2*kc][0], ph[2*kc][1], ph[2*kc+1][0], ph[2*kc+1][1] };
            #pragma unroll
            for (int jd = 0; jd < 8; jd += 2) {
                int row = 16*kc + ((lane >> 3) & 1)*8 + (lane & 7);
                int col = 8*jd + ((lane >> 4) << 3);
                uint32_t addr = (uint32_t)__cvta_generic_to_shared(Vs + row*HTS + col);
                uint32_t v0, v1, v2, v3;
                asm volatile(
                    "ldmatrix.sync.aligned.m8n8.x4.trans.shared.b16 {%0,%1,%2,%3}, [%4];"
                    : "=r"(v0), "=r"(v1), "=r"(v2), "=r"(v3) : "r"(addr));
                mma16816(oac[jd],   af, v0, v1);
                mma16816(oac[jd+1], af, v2, v3);
            }
        }
    }

    // reduce row sums over the quad (t = 0..3)
    rs0 += __shfl_xor_sync(0xffffffffu, rs0, 1);
    rs0 += __shfl_xor_sync(0xffffffffu, rs0, 2);
    rs1 += __shfl_xor_sync(0xffffffffu, rs1, 1);
    rs1 += __shfl_xor_sync(0xffffffffu, rs1, 2);

    if (SPLIT) {
        int pidx = ((b*HEADS + h)*QBY + qb)*NSPLIT + sp;
        float* dst0 = pO + (size_t)pidx*(128*64) + (w*16 + g)*64;
        float* dst1 = dst0 + 8*64;
        #pragma unroll
        for (int jd = 0; jd < 8; jd++) {
            int col = 8*jd + 2*t;
            *(float2*)(dst0 + col) = make_float2(oac[jd][0], oac[jd][1]);
            *(float2*)(dst1 + col) = make_float2(oac[jd][2], oac[jd][3]);
        }
        if (t == 0) {
            pL[pidx*128 + w*16 + g]     = rs0;
            pL[pidx*128 + w*16 + g + 8] = rs1;
        }
    } else {
        float inv0 = 1.f / rs0;
        float inv1 = 1.f / rs1;
        __half* orow0 = attno + (size_t)(b*MTOK + q0 + w*16 + g)*DIMC + h*HD;
        __half* orow1 = orow0 + 8*DIMC;
        #pragma unroll
        for (int jd = 0; jd < 8; jd++) {
            int col = 8*jd + 2*t;
            *(uint32_t*)(orow0 + col) = pack_h2(oac[jd][0]*inv0, oac[jd][1]*inv0);
            *(uint32_t*)(orow1 + col) = pack_h2(oac[jd][2]*inv1, oac[jd][3]*inv1);
        }
    }
}

// ---------------- merge split-K partials ----------------
__global__ void __launch_bounds__(128) merge_attn(
    const float* __restrict__ pO, const float* __restrict__ pL,
    __half* __restrict__ attno)
{
    int qb = blockIdx.x, h = blockIdx.y, b = blockIdx.z;
    int r = threadIdx.x;
    int base = ((b*HEADS + h)*QBY + qb)*NSPLIT;

    float L = 0.f;
    #pragma unroll
    for (int s = 0; s < NSPLIT; s++) L += pL[(base+s)*128 + r];
    float inv = 1.f / L;

    int qi = NX + (qb << 7) + r;
    __half* op = attno + ((size_t)(b*MTOK + qi))*DIMC + h*HD;
    #pragma unroll 4
    for (int c = 0; c < 64; c++) {
        float o = 0.f;
        #pragma unroll
        for (int s = 0; s < NSPLIT; s++)
            o += pO[(size_t)(base+s)*(128*64) + r*64 + c];
        op[c] = __float2half(o * inv);
    }
}

// ---------------- launch ----------------
extern "C" void kernel_launch(void* const* d_in, const int* in_sizes, int n_in,
                              void* d_out, int out_size)
{
    const float* x     = (const float*)d_in[0];
    const float* y     = (const float*)d_in[1];
    const float* n1w   = (const float*)d_in[2];
    const float* n1b   = (const float*)d_in[3];
    const float* n2w   = (const float*)d_in[4];
    const float* n2b   = (const float*)d_in[5];
    const float* qkvw  = (const float*)d_in[6];
    const float* projw = (const float*)d_in[7];
    const float* projb = (const float*)d_in[8];
    const float* fc1w  = (const float*)d_in[9];
    const float* fc1bb = (const float*)d_in[10];
    const float* fc2w  = (const float*)d_in[11];
    const float* fc2b  = (const float*)d_in[12];
    (void)in_sizes; (void)n_in; (void)out_size;

    float* outx = (float*)d_out;
    float* outy = outx + (size_t)BATCH*NX*DIMC;

    __half *catln, *qkvh, *attno, *ln2o, *fc1o, *wrnd;
    float *pO, *pL;
    cudaGetSymbolAddress((void**)&catln, g_catln);
    cudaGetSymbolAddress((void**)&qkvh,  g_qkvh);
    cudaGetSymbolAddress((void**)&attno, g_attno);
    cudaGetSymbolAddress((void**)&ln2o,  g_ln2);
    cudaGetSymbolAddress((void**)&fc1o,  g_fc1);
    cudaGetSymbolAddress((void**)&wrnd,  g_wrnd);
    cudaGetSymbolAddress((void**)&pO,    g_pO);
    cudaGetSymbolAddress((void**)&pL,    g_pL);

    cudaFuncSetAttribute(gemm_fp16<0>, cudaFuncAttributeMaxDynamicSharedMemorySize, SMEM_GEMM);
    cudaFuncSetAttribute(gemm_fp16<1>, cudaFuncAttributeMaxDynamicSharedMemorySize, SMEM_GEMM);
    cudaFuncSetAttribute(gemm_fp16<2>, cudaFuncAttributeMaxDynamicSharedMemorySize, SMEM_GEMM);
    cudaFuncSetAttribute(gemm_fp16<3>, cudaFuncAttributeMaxDynamicSharedMemorySize, SMEM_GEMM);

    // 0) pre-round weights to fp16
    round_weights<<<256, 256>>>(qkvw, projw, fc1w, fc2w, wrnd);
    // 1) LN1 over concat(x, y)  — warp-per-token
    ln_fast<<<TTOK/8, 256>>>(x, y, n1w, n1b, catln);
    // 2) fused QKV GEMM (fp16)
    gemm_fp16<0><<<dim3(QKVN/64, TTOK/128), 256, SMEM_GEMM>>>(catln, wrnd + OFF_QKVW, nullptr, qkvh,
        TTOK, QKVN, DIMC, nullptr, nullptr, nullptr, nullptr);
    // 3) x self-attention (register-resident PTX flash)
    attn_v5<false><<<dim3(NX/128, HEADS, BATCH), 256, SMEM_ATTN5>>>(qkvh, attno, nullptr, nullptr, 0, NX);
    // 4) y cross-attention: split-K x4 + merge
    attn_v5<true><<<dim3(QBY*NSPLIT, HEADS, BATCH), 256, SMEM_ATTN5>>>(qkvh, nullptr, pO, pL, NX, KSPLIT);
    merge_attn<<<dim3(QBY, HEADS, BATCH), 128>>>(pO, pL, attno);
    // 5) output projection + bias + input residual -> d_out
    gemm_fp16<1><<<dim3(DIMC/64, TTOK/128), 256, SMEM_GEMM>>>(attno, wrnd + OFF_PROJW, projb, nullptr,
        TTOK, DIMC, DIMC, x, y, outx, outy);
    // 6) LN2 over d_out — warp-per-token
    ln_fast<<<TTOK/8, 256>>>(outx, outy, n2w, n2b, ln2o);
    // 7) fc1 + bias + exact GELU
    gemm_fp16<2><<<dim3(HIDDEN/64, TTOK/128), 256, SMEM_GEMM>>>(ln2o, wrnd + OFF_FC1W, fc1bb, fc1o,
        TTOK, HIDDEN, DIMC, nullptr, nullptr, nullptr, nullptr);
    // 8) fc2 + bias + residual (in place on d_out)
    gemm_fp16<3><<<dim3(DIMC/64, TTOK/128), 256, SMEM_GEMM>>>(fc1o, wrnd + OFF_FC2W, fc2b, nullptr,
        TTOK, DIMC, HIDDEN, nullptr, nullptr, outx, outy);
}